// round 12
// baseline (speedup 1.0000x reference)
#include <cuda_runtime.h>
#include <math.h>

// ---------------------------------------------------------------------------
// SCRFD post-processing, 4 graph nodes:
//   1) decode (bit-exact, dbl-precision sigmoid key)
//   2) counting-sort argsort (1 block, exact stable, all-smem bookkeeping)
//   3) suppression edges + unmasked outputs (chip-wide)
//   4) NMS fixpoint + masked fixup + keep column (1 block)
//
// Output layout (float32, 134400 elems):
//   [0:33600) boxes[8400,4] | [33600:42000) scores | [42000:126000) kps[8400,10]
//   | [126000:134400) keep
// ---------------------------------------------------------------------------

#define NTOT    8400
#define NBUCK   2048
#define SCORE_T 0.5f
#define NMS_T   0.4f
#define EDGE_CAP (1 << 22)
#define ESMEM   4096          // edges cached in smem when ne <= this
#define EBLK    264           // edge-kernel blocks
#define ETHR    256

typedef unsigned long long u64;
typedef unsigned int u32;
typedef unsigned char uc;

__device__ float4 g_box[NTOT];         // decoded boxes (orig order)
__device__ float  g_kps[NTOT * 10];    // decoded keypoints (orig order)
__device__ u32    g_key32[NTOT];       // sigmoid f32 bits (positive)
__device__ u64    g_bitem[NTOT];       // bucket-grouped (key<<14)|(8399-n)
__device__ float  g_skey[NTOT];        // sorted scores
__device__ int    g_sidx[NTOT];        // sorted -> orig index
__device__ float4 g_sbox[NTOT];        // sorted boxes
__device__ float  g_area[NTOT];        // sorted areas
__device__ int    g_nvalid;            // #scores > SCORE_T (sorted prefix)
__device__ int    g_nedges;
__device__ u32    g_edges[EDGE_CAP];   // (i<<16)|j, j<i<nvalid, IoU>NMS_T

// ---------------------------------------------------------------------------
__global__ void decode_kernel(const float* __restrict__ s0, const float* __restrict__ b0, const float* __restrict__ k0,
                              const float* __restrict__ s1, const float* __restrict__ b1, const float* __restrict__ k1,
                              const float* __restrict__ s2, const float* __restrict__ b2, const float* __restrict__ k2)
{
    int n = blockIdx.x * blockDim.x + threadIdx.x;
    if (n == 0) g_nedges = 0;             // reset for this replay (precedes edge)
    if (n >= NTOT) return;

    const float *sp, *bp, *kp;
    int local, fw;
    float st;
    if (n < 6400)      { sp = s0; bp = b0; kp = k0; local = n;        fw = 80; st = 8.0f;  }
    else if (n < 8000) { sp = s1; bp = b1; kp = k1; local = n - 6400; fw = 40; st = 16.0f; }
    else               { sp = s2; bp = b2; kp = k2; local = n - 8000; fw = 20; st = 32.0f; }

    float px = (float)(local % fw) * st;  // exact (int * pow2)
    float py = (float)(local / fw) * st;

    // sigmoid in double: correctly-rounded-to-f32 -> monotone ordering
    // (ordering matches JAX; rel_err 4.3e-8 across R7-R10).
    float s = (float)(1.0 / (1.0 + exp(-(double)sp[local])));

    float4 d = ((const float4*)bp)[local];   // pow2 strides -> bit-exact decode
    float4 bb;
    bb.x = px - d.x * st;
    bb.y = py - d.y * st;
    bb.z = px + d.z * st;
    bb.w = py + d.w * st;
    g_box[n] = bb;

    const float2* kp2 = (const float2*)kp;   // 10 floats = 5 x float2
#pragma unroll
    for (int q = 0; q < 5; q++) {
        float2 kv = kp2[local * 5 + q];
        g_kps[n * 10 + 2 * q + 0] = px + kv.x * st;
        g_kps[n * 10 + 2 * q + 1] = py + kv.y * st;
    }

    g_key32[n] = __float_as_uint(s);      // positive -> uint order == float order
}

// ---------------------------------------------------------------------------
// Exact stable argsort (score desc, idx asc) by value-uniform counting sort:
// bucket(s) = floor(s*2048) is monotone nondecreasing in s, so buckets are
// contiguous in sorted order; within-bucket exact rank via strict-total-order
// pack compares ((key<<14)|(8399-n), avg ~4 per item). Single block, smem
// bookkeeping only (nothing persists -> nothing to reset between replays).
__global__ void sort_kernel()
{
    __shared__ u32 hist[NBUCK];
    __shared__ u32 base[NBUCK];
    __shared__ u32 cur[NBUCK];
    __shared__ u32 scanbuf[1024];
    __shared__ int nval;

    int tid = threadIdx.x;
    for (int b = tid; b < NBUCK; b += 1024) { hist[b] = 0; cur[b] = 0; }
    if (tid == 0) nval = 0;
    __syncthreads();

    // histogram (value-space buckets)
    for (int n = tid; n < NTOT; n += 1024) {
        float s = __uint_as_float(g_key32[n]);
        u32 b = (u32)(s * (float)NBUCK);
        if (b > NBUCK - 1) b = NBUCK - 1;
        atomicAdd(&hist[b], 1u);
    }
    __syncthreads();

    // descending exclusive scan: thread t owns descending slots {2t, 2t+1}
    u32 l0 = hist[NBUCK - 1 - (tid * 2)];
    u32 l1 = hist[NBUCK - 1 - (tid * 2 + 1)];
    u32 s2 = l0 + l1;
    scanbuf[tid] = s2;
    __syncthreads();
    for (int off = 1; off < 1024; off <<= 1) {
        u32 v = scanbuf[tid];
        u32 add = (tid >= off) ? scanbuf[tid - off] : 0u;
        __syncthreads();
        scanbuf[tid] = v + add;
        __syncthreads();
    }
    u32 run = scanbuf[tid] - s2;
    base[NBUCK - 1 - (tid * 2)]     = run;
    base[NBUCK - 1 - (tid * 2 + 1)] = run + l0;
    __syncthreads();

    // fill bucket lists (slot order irrelevant)
    for (int n = tid; n < NTOT; n += 1024) {
        u32 key = g_key32[n];
        float s = __uint_as_float(key);
        u32 b = (u32)(s * (float)NBUCK);
        if (b > NBUCK - 1) b = NBUCK - 1;
        u32 slot = atomicAdd(&cur[b], 1u);
        g_bitem[base[b] + slot] = ((u64)key << 14) | (u32)(NTOT - 1 - n);
    }
    __syncthreads();

    // exact within-bucket rank + scatter
    for (int n = tid; n < NTOT; n += 1024) {
        u32 key = g_key32[n];
        float s = __uint_as_float(key);
        u32 b = (u32)(s * (float)NBUCK);
        if (b > NBUCK - 1) b = NBUCK - 1;
        u32 bs = base[b], L = hist[b];
        u64 me = ((u64)key << 14) | (u32)(NTOT - 1 - n);
        u32 c = 0;
        for (u32 l = 0; l < L; l++)
            c += (g_bitem[bs + l] > me) ? 1u : 0u;
        u32 r = bs + c;
        g_skey[r] = s;
        g_sidx[r] = n;
        float4 bx = g_box[n];
        g_sbox[r] = bx;
        g_area[r] = __fmul_rn(__fsub_rn(bx.z, bx.x), __fsub_rn(bx.w, bx.y));
        if (s > SCORE_T) atomicAdd(&nval, 1);
    }
    __syncthreads();
    if (tid == 0) g_nvalid = nval;
}

// ---------------------------------------------------------------------------
// Suppression edges (i,j): j<i<nvalid, IoU>NMS_T (validity is a prefix of the
// descending sort). Striped rows over EBLK blocks. Also writes all UNMASKED
// outputs (node 4 only fixes suppressed rows + keep column).
// IoU replicates JAX bit-for-bit (rn intrinsics block FMA contraction).
__global__ void edge_kernel(float* __restrict__ out)
{
    int tid = threadIdx.x;
    int nv = g_nvalid;

    for (int i = 1 + blockIdx.x; i < nv; i += EBLK) {
        float4 bi = g_sbox[i];
        float  ai = g_area[i];
        for (int j = tid; j < i; j += ETHR) {
            float4 bj = g_sbox[j];
            float ltx = fmaxf(bi.x, bj.x);
            float lty = fmaxf(bi.y, bj.y);
            float rbx = fminf(bi.z, bj.z);
            float rby = fminf(bi.w, bj.w);
            float w = fmaxf(__fsub_rn(rbx, ltx), 0.0f);
            float h = fmaxf(__fsub_rn(rby, lty), 0.0f);
            float inter = __fmul_rn(w, h);
            if (inter > 0.0f) {
                float denom = __fadd_rn(__fsub_rn(__fadd_rn(ai, g_area[j]), inter), 1e-9f);
                float iou = __fdiv_rn(inter, denom);
                if (iou > NMS_T) {
                    int pos = atomicAdd(&g_nedges, 1);
                    if (pos < EDGE_CAP) g_edges[pos] = ((u32)i << 16) | (u32)j;
                }
            }
        }
    }

    // unmasked outputs (one pass, chip-wide)
    for (int p = blockIdx.x * ETHR + tid; p < NTOT; p += EBLK * ETHR) {
        float4 b = g_sbox[p];
        out[p * 4 + 0] = b.x;
        out[p * 4 + 1] = b.y;
        out[p * 4 + 2] = b.z;
        out[p * 4 + 3] = b.w;
        out[33600 + p] = g_skey[p];
        int j = g_sidx[p];
#pragma unroll
        for (int q = 0; q < 10; q++)
            out[42000 + p * 10 + q] = g_kps[j * 10 + q];
    }
}

// ---------------------------------------------------------------------------
// Greedy NMS = unique fixpoint of keep[i] = valid[i] && !any((i,j): keep[j])
// on the j<i DAG. Edge-centric Jacobi in smem; "no change" = exact; NTOT+1
// cap is a hard guarantee. Then fix up suppressed rows + keep column.
__global__ void nms_kernel(float* __restrict__ out)
{
    __shared__ u32 es[ESMEM];
    __shared__ uc keep[NTOT];
    __shared__ uc sup[NTOT];
    __shared__ int changed;

    int tid = threadIdx.x;
    int nv = g_nvalid;
    int ne = g_nedges;
    if (ne > EDGE_CAP) ne = EDGE_CAP;
    bool use_s = (ne <= ESMEM);
    if (use_s)
        for (int e = tid; e < ne; e += blockDim.x) es[e] = g_edges[e];
    for (int p = tid; p < NTOT; p += blockDim.x)
        keep[p] = (p < nv) ? 1 : 0;          // valid prefix
    __syncthreads();
    const u32* E = use_s ? es : g_edges;

    for (int it = 0; it < NTOT + 1; it++) {
        if (tid == 0) changed = 0;
        for (int e = tid; e < ne; e += blockDim.x) sup[E[e] >> 16] = 0;
        __syncthreads();
        for (int e = tid; e < ne; e += blockDim.x) {
            u32 x = E[e];
            if (keep[x & 0xffffu]) sup[x >> 16] = 1;
        }
        __syncthreads();
        for (int e = tid; e < ne; e += blockDim.x) {
            int i = (int)(E[e] >> 16);
            uc nvz = (!sup[i]) ? 1 : 0;      // i < nv by construction
            if (keep[i] != nvz) { keep[i] = nvz; changed = 1; }
        }
        __syncthreads();
        int ch = changed;
        __syncthreads();
        if (!ch) break;
    }

    // masked fixup: zero suppressed/invalid rows, write keep column
    for (int p = tid; p < NTOT; p += blockDim.x) {
        uc m = keep[p];
        out[126000 + p] = m ? 1.0f : 0.0f;
        if (!m) {
            out[p * 4 + 0] = 0.0f;
            out[p * 4 + 1] = 0.0f;
            out[p * 4 + 2] = 0.0f;
            out[p * 4 + 3] = 0.0f;
            out[33600 + p] = 0.0f;
#pragma unroll
            for (int q = 0; q < 10; q++)
                out[42000 + p * 10 + q] = 0.0f;
        }
    }
}

// ---------------------------------------------------------------------------
extern "C" void kernel_launch(void* const* d_in, const int* in_sizes, int n_in,
                              void* d_out, int out_size)
{
    const float *s0, *b0, *k0, *s1, *b1, *k1, *s2, *b2, *k2;
    // dict-insertion order (score0,bbox0,kps0,...) vs signature order
    if (n_in >= 9 && in_sizes[1] == 25600) {
        s0 = (const float*)d_in[0]; b0 = (const float*)d_in[1]; k0 = (const float*)d_in[2];
        s1 = (const float*)d_in[3]; b1 = (const float*)d_in[4]; k1 = (const float*)d_in[5];
        s2 = (const float*)d_in[6]; b2 = (const float*)d_in[7]; k2 = (const float*)d_in[8];
    } else {
        s0 = (const float*)d_in[0]; s1 = (const float*)d_in[1]; s2 = (const float*)d_in[2];
        b0 = (const float*)d_in[3]; b1 = (const float*)d_in[4]; b2 = (const float*)d_in[5];
        k0 = (const float*)d_in[6]; k1 = (const float*)d_in[7]; k2 = (const float*)d_in[8];
    }

    decode_kernel<<<(NTOT + 255) / 256, 256>>>(s0, b0, k0, s1, b1, k1, s2, b2, k2);
    sort_kernel<<<1, 1024>>>();
    edge_kernel<<<EBLK, ETHR>>>((float*)d_out);
    nms_kernel<<<1, 1024>>>((float*)d_out);
}

// round 13
// speedup vs baseline: 1.4633x; 1.4633x over previous
#include <cuda_runtime.h>
#include <math.h>

// ---------------------------------------------------------------------------
// SCRFD post-processing, 4 graph nodes:
//   1) decode (bit-exact) + zero-fill d_out + counter resets
//   2) counting-sort argsort (1 block, exact stable) + candidate compaction
//      (candidate = valid(score>0.5) AND proper(x2>x1 && y2>y1); improper
//       boxes have iou==0 vs everything -> participate in no edges)
//   3) pairwise edges over smem-resident candidates + unmasked valid-row out
//   4) NMS fixpoint (smem edge-list Jacobi) + suppressed-row zeroing + keep
//
// Output layout (float32, 134400 elems):
//   [0:33600) boxes[8400,4] | [33600:42000) scores | [42000:126000) kps[8400,10]
//   | [126000:134400) keep
// ---------------------------------------------------------------------------

#define NTOT    8400
#define NBUCK   2048
#define SCORE_T 0.5f
#define NMS_T   0.4f
#define EDGE_CAP (1 << 22)
#define ESMEM   16384         // smem edge cache (ne bracketed to <=16384 in R9)
#define CAND_CAP 3072         // >>67 sigma above mean ~1050
#define EBLK    132
#define ETHR    256

typedef unsigned long long u64;
typedef unsigned int u32;
typedef unsigned char uc;

__device__ float4 g_box[NTOT];         // decoded boxes (orig order)
__device__ float  g_kps[NTOT * 10];    // decoded keypoints (orig order)
__device__ u32    g_key32[NTOT];       // sigmoid f32 bits (positive)
__device__ u64    g_bitem[NTOT];       // bucket-grouped (key<<14)|(8399-n)
__device__ float  g_skey[NTOT];        // sorted scores
__device__ int    g_sidx[NTOT];        // sorted -> orig index
__device__ float4 g_sbox[NTOT];        // sorted boxes
__device__ float  g_area[NTOT];        // sorted areas
__device__ int    g_nvalid;            // #scores > SCORE_T (sorted prefix)
__device__ int    g_ncand;             // #candidates (valid & proper)
__device__ u32    g_cand[CAND_CAP];    // candidate sorted-positions (unordered)
__device__ int    g_nedges;
__device__ u32    g_edges[EDGE_CAP];   // (i<<16)|j, j<i, IoU>NMS_T

// ---------------------------------------------------------------------------
__global__ void decode_kernel(const float* __restrict__ s0, const float* __restrict__ b0, const float* __restrict__ k0,
                              const float* __restrict__ s1, const float* __restrict__ b1, const float* __restrict__ k1,
                              const float* __restrict__ s2, const float* __restrict__ b2, const float* __restrict__ k2,
                              float* __restrict__ out)
{
    int n = blockIdx.x * blockDim.x + threadIdx.x;
    if (n == 0) { g_nedges = 0; g_ncand = 0; }   // reset for this replay

    // zero-fill the whole output (later nodes overwrite live rows)
    float4 z = make_float4(0.f, 0.f, 0.f, 0.f);
    float4* o4 = (float4*)out;
    for (int q = n; q < 134400 / 4; q += gridDim.x * blockDim.x) o4[q] = z;

    if (n >= NTOT) return;

    const float *sp, *bp, *kp;
    int local, fw;
    float st;
    if (n < 6400)      { sp = s0; bp = b0; kp = k0; local = n;        fw = 80; st = 8.0f;  }
    else if (n < 8000) { sp = s1; bp = b1; kp = k1; local = n - 6400; fw = 40; st = 16.0f; }
    else               { sp = s2; bp = b2; kp = k2; local = n - 8000; fw = 20; st = 32.0f; }

    float px = (float)(local % fw) * st;  // exact (int * pow2)
    float py = (float)(local / fw) * st;

    // sigmoid in double: correctly-rounded-to-f32 -> monotone ordering
    // (matches JAX ordering; rel_err 4.3e-8 across R7-R11).
    float s = (float)(1.0 / (1.0 + exp(-(double)sp[local])));

    float4 d = ((const float4*)bp)[local];   // pow2 strides -> bit-exact decode
    float4 bb;
    bb.x = px - d.x * st;
    bb.y = py - d.y * st;
    bb.z = px + d.z * st;
    bb.w = py + d.w * st;
    g_box[n] = bb;

    const float2* kp2 = (const float2*)kp;   // 10 floats = 5 x float2
#pragma unroll
    for (int q = 0; q < 5; q++) {
        float2 kv = kp2[local * 5 + q];
        g_kps[n * 10 + 2 * q + 0] = px + kv.x * st;
        g_kps[n * 10 + 2 * q + 1] = py + kv.y * st;
    }

    g_key32[n] = __float_as_uint(s);      // positive -> uint order == float order
}

// ---------------------------------------------------------------------------
// Exact stable argsort (score desc, idx asc) via value-space counting sort:
// bucket(s) = floor(s*2048) (mul by pow2 = exact scaling -> monotone), then
// exact within-bucket rank via strict-total-order pack (key<<14)|(8399-n).
// Also compacts candidates: sorted positions with s>SCORE_T AND proper box.
__global__ void sort_kernel()
{
    __shared__ u32 hist[NBUCK];
    __shared__ u32 base[NBUCK];
    __shared__ u32 cur[NBUCK];
    __shared__ u32 scanbuf[1024];
    __shared__ int nval, ncan;

    int tid = threadIdx.x;
    for (int b = tid; b < NBUCK; b += 1024) { hist[b] = 0; cur[b] = 0; }
    if (tid == 0) { nval = 0; ncan = 0; }
    __syncthreads();

    // histogram + valid count
    for (int n = tid; n < NTOT; n += 1024) {
        float s = __uint_as_float(g_key32[n]);
        u32 b = (u32)(s * (float)NBUCK);
        if (b > NBUCK - 1) b = NBUCK - 1;
        atomicAdd(&hist[b], 1u);
        if (s > SCORE_T) atomicAdd(&nval, 1);
    }
    __syncthreads();

    // descending exclusive scan: thread t owns descending slots {2t, 2t+1}
    u32 l0 = hist[NBUCK - 1 - (tid * 2)];
    u32 l1 = hist[NBUCK - 1 - (tid * 2 + 1)];
    u32 s2 = l0 + l1;
    scanbuf[tid] = s2;
    __syncthreads();
    for (int off = 1; off < 1024; off <<= 1) {
        u32 v = scanbuf[tid];
        u32 add = (tid >= off) ? scanbuf[tid - off] : 0u;
        __syncthreads();
        scanbuf[tid] = v + add;
        __syncthreads();
    }
    u32 run = scanbuf[tid] - s2;
    base[NBUCK - 1 - (tid * 2)]     = run;
    base[NBUCK - 1 - (tid * 2 + 1)] = run + l0;
    __syncthreads();

    // fill bucket lists (slot order irrelevant)
    for (int n = tid; n < NTOT; n += 1024) {
        u32 key = g_key32[n];
        float s = __uint_as_float(key);
        u32 b = (u32)(s * (float)NBUCK);
        if (b > NBUCK - 1) b = NBUCK - 1;
        u32 slot = atomicAdd(&cur[b], 1u);
        g_bitem[base[b] + slot] = ((u64)key << 14) | (u32)(NTOT - 1 - n);
    }
    __syncthreads();

    // exact within-bucket rank + scatter
    for (int n = tid; n < NTOT; n += 1024) {
        u32 key = g_key32[n];
        float s = __uint_as_float(key);
        u32 b = (u32)(s * (float)NBUCK);
        if (b > NBUCK - 1) b = NBUCK - 1;
        u32 bs = base[b], L = hist[b];
        u64 me = ((u64)key << 14) | (u32)(NTOT - 1 - n);
        u32 c = 0;
        for (u32 l = 0; l < L; l++)
            c += (g_bitem[bs + l] > me) ? 1u : 0u;
        u32 r = bs + c;
        g_skey[r] = s;
        g_sidx[r] = n;
        float4 bx = g_box[n];
        g_sbox[r] = bx;
        g_area[r] = __fmul_rn(__fsub_rn(bx.z, bx.x), __fsub_rn(bx.w, bx.y));

        // candidate = valid AND proper; improper boxes have iou==0 with all.
        if (s > SCORE_T && bx.z > bx.x && bx.w > bx.y) {
            int c2 = atomicAdd(&ncan, 1);
            if (c2 < CAND_CAP) g_cand[c2] = r;
        }
    }
    __syncthreads();
    if (tid == 0) { g_nvalid = nval; g_ncand = ncan; }
}

// ---------------------------------------------------------------------------
// Edges over the compacted candidate set, smem-resident: each unordered pair
// of candidates once (list index b < a; list order irrelevant since edge uses
// i=max(r), j=min(r)). IoU replicates JAX bit-for-bit.
// Also writes unmasked outputs for the valid prefix (NMS re-zeros suppressed).
__global__ void edge_kernel(float* __restrict__ out)
{
    extern __shared__ char sm[];
    float4* cb = (float4*)sm;                  // [CAND_CAP] boxes
    float*  ca = (float*)(cb + CAND_CAP);      // [CAND_CAP] areas
    u32*    cr = (u32*)(ca + CAND_CAP);        // [CAND_CAP] sorted positions

    int tid = threadIdx.x;
    int nc = g_ncand;
    int nv = g_nvalid;

    if (nc <= CAND_CAP) {
        for (int t = tid; t < nc; t += ETHR) {
            u32 r = g_cand[t];
            cr[t] = r;
            cb[t] = g_sbox[r];
            ca[t] = g_area[r];
        }
        __syncthreads();

        for (int a = blockIdx.x; a < nc; a += EBLK) {
            float4 bi = cb[a];
            float  ai = ca[a];
            u32    ri = cr[a];
            for (int b = tid; b < a; b += ETHR) {
                float4 bj = cb[b];
                float ltx = fmaxf(bi.x, bj.x);
                float lty = fmaxf(bi.y, bj.y);
                float rbx = fminf(bi.z, bj.z);
                float rby = fminf(bi.w, bj.w);
                float w = fmaxf(__fsub_rn(rbx, ltx), 0.0f);
                float h = fmaxf(__fsub_rn(rby, lty), 0.0f);
                float inter = __fmul_rn(w, h);
                if (inter > 0.0f) {
                    float denom = __fadd_rn(__fsub_rn(__fadd_rn(ai, ca[b]), inter), 1e-9f);
                    float iou = __fdiv_rn(inter, denom);
                    if (iou > NMS_T) {
                        u32 rj = cr[b];
                        u32 hi = ri > rj ? ri : rj;
                        u32 lo = ri > rj ? rj : ri;
                        int pos = atomicAdd(&g_nedges, 1);
                        if (pos < EDGE_CAP) g_edges[pos] = (hi << 16) | lo;
                    }
                }
            }
        }
    } else {
        // fallback: row-wise over valid prefix (correct for any data)
        for (int i = 1 + blockIdx.x; i < nv; i += EBLK) {
            float4 bi = g_sbox[i];
            if (!(bi.z > bi.x && bi.w > bi.y)) continue;
            float ai = g_area[i];
            for (int j = tid; j < i; j += ETHR) {
                float4 bj = g_sbox[j];
                float ltx = fmaxf(bi.x, bj.x);
                float lty = fmaxf(bi.y, bj.y);
                float rbx = fminf(bi.z, bj.z);
                float rby = fminf(bi.w, bj.w);
                float w = fmaxf(__fsub_rn(rbx, ltx), 0.0f);
                float h = fmaxf(__fsub_rn(rby, lty), 0.0f);
                float inter = __fmul_rn(w, h);
                if (inter > 0.0f) {
                    float denom = __fadd_rn(__fsub_rn(__fadd_rn(ai, g_area[j]), inter), 1e-9f);
                    float iou = __fdiv_rn(inter, denom);
                    if (iou > NMS_T) {
                        int pos = atomicAdd(&g_nedges, 1);
                        if (pos < EDGE_CAP) g_edges[pos] = ((u32)i << 16) | (u32)j;
                    }
                }
            }
        }
    }

    // unmasked outputs for the valid prefix (rest of out already zero)
    for (int p = blockIdx.x * ETHR + tid; p < nv; p += EBLK * ETHR) {
        float4 b = g_sbox[p];
        out[p * 4 + 0] = b.x;
        out[p * 4 + 1] = b.y;
        out[p * 4 + 2] = b.z;
        out[p * 4 + 3] = b.w;
        out[33600 + p] = g_skey[p];
        int j = g_sidx[p];
#pragma unroll
        for (int q = 0; q < 10; q++)
            out[42000 + p * 10 + q] = g_kps[j * 10 + q];
    }
}

// ---------------------------------------------------------------------------
// Greedy NMS = unique fixpoint of keep[i] = valid[i] && !any((i,j): keep[j])
// on the j<i DAG. Edge-centric Jacobi in smem; "no change" = exact; NTOT+1
// cap is a hard guarantee. Fixup: zero suppressed rows, set keep=1 for kept.
__global__ void nms_kernel(float* __restrict__ out)
{
    extern __shared__ char sm[];
    u32* es   = (u32*)sm;                      // [ESMEM]
    uc*  keep = (uc*)(es + ESMEM);             // [NTOT]
    uc*  sup  = keep + NTOT;                   // [NTOT]
    __shared__ int changed;

    int tid = threadIdx.x;
    int nv = g_nvalid;
    int ne = g_nedges;
    if (ne > EDGE_CAP) ne = EDGE_CAP;
    bool use_s = (ne <= ESMEM);
    if (use_s)
        for (int e = tid; e < ne; e += blockDim.x) es[e] = g_edges[e];
    for (int p = tid; p < NTOT; p += blockDim.x)
        keep[p] = (p < nv) ? 1 : 0;            // valid prefix
    __syncthreads();
    const u32* E = use_s ? es : g_edges;

    for (int it = 0; it < NTOT + 1; it++) {
        if (tid == 0) changed = 0;
        for (int e = tid; e < ne; e += blockDim.x) sup[E[e] >> 16] = 0;
        __syncthreads();
        for (int e = tid; e < ne; e += blockDim.x) {
            u32 x = E[e];
            if (keep[x & 0xffffu]) sup[x >> 16] = 1;
        }
        __syncthreads();
        for (int e = tid; e < ne; e += blockDim.x) {
            int i = (int)(E[e] >> 16);
            uc nz = (!sup[i]) ? 1 : 0;         // i < nv by construction
            if (keep[i] != nz) { keep[i] = nz; changed = 1; }
        }
        __syncthreads();
        int ch = changed;
        __syncthreads();
        if (!ch) break;
    }

    // fixup: kept rows get keep=1; suppressed valid rows get re-zeroed.
    for (int p = tid; p < nv; p += blockDim.x) {
        if (keep[p]) {
            out[126000 + p] = 1.0f;
        } else {
            out[p * 4 + 0] = 0.0f;
            out[p * 4 + 1] = 0.0f;
            out[p * 4 + 2] = 0.0f;
            out[p * 4 + 3] = 0.0f;
            out[33600 + p] = 0.0f;
#pragma unroll
            for (int q = 0; q < 10; q++)
                out[42000 + p * 10 + q] = 0.0f;
        }
    }
}

// ---------------------------------------------------------------------------
extern "C" void kernel_launch(void* const* d_in, const int* in_sizes, int n_in,
                              void* d_out, int out_size)
{
    const float *s0, *b0, *k0, *s1, *b1, *k1, *s2, *b2, *k2;
    // dict-insertion order (score0,bbox0,kps0,...) vs signature order
    if (n_in >= 9 && in_sizes[1] == 25600) {
        s0 = (const float*)d_in[0]; b0 = (const float*)d_in[1]; k0 = (const float*)d_in[2];
        s1 = (const float*)d_in[3]; b1 = (const float*)d_in[4]; k1 = (const float*)d_in[5];
        s2 = (const float*)d_in[6]; b2 = (const float*)d_in[7]; k2 = (const float*)d_in[8];
    } else {
        s0 = (const float*)d_in[0]; s1 = (const float*)d_in[1]; s2 = (const float*)d_in[2];
        b0 = (const float*)d_in[3]; b1 = (const float*)d_in[4]; b2 = (const float*)d_in[5];
        k0 = (const float*)d_in[6]; k1 = (const float*)d_in[7]; k2 = (const float*)d_in[8];
    }

    const int edge_smem = CAND_CAP * (16 + 4 + 4);          // 73,728 B
    const int nms_smem  = ESMEM * 4 + 2 * NTOT;             // 82,336 B
    cudaFuncSetAttribute(edge_kernel, cudaFuncAttributeMaxDynamicSharedMemorySize, edge_smem);
    cudaFuncSetAttribute(nms_kernel,  cudaFuncAttributeMaxDynamicSharedMemorySize, nms_smem);

    decode_kernel<<<33, 256>>>(s0, b0, k0, s1, b1, k1, s2, b2, k2, (float*)d_out);
    sort_kernel<<<1, 1024>>>();
    edge_kernel<<<EBLK, ETHR, edge_smem>>>((float*)d_out);
    nms_kernel<<<1, 1024, nms_smem>>>((float*)d_out);
}

// round 14
// speedup vs baseline: 1.9727x; 1.3481x over previous
#include <cuda_runtime.h>
#include <math.h>

// ---------------------------------------------------------------------------
// SCRFD post-processing in TWO graph nodes (spin-free last-block pattern):
//   K1: decode + zero-fill out (all blocks); LAST block: counting-sort argsort
//       (exact, stable) -> g_perm + candidate compaction + counter resets
//   K2: candidate pair sweep -> edge list + unmasked valid-prefix output
//       (all blocks); LAST block: smem Jacobi NMS + suppressed-row fixup
//
// Output layout (float32, 134400 elems):
//   [0:33600) boxes[8400,4] | [33600:42000) scores | [42000:126000) kps[8400,10]
//   | [126000:134400) keep
// ---------------------------------------------------------------------------

#define NTOT    8400
#define NBLK    132
#define NTHR1   1024
#define NTHR2   512
#define NBUCK   2048
#define SCORE_T 0.5f
#define NMS_T   0.4f
#define EDGE_CAP (1 << 22)
#define ESMEM   16384        // smem edge cache (ne bracketed <=16384 in R9/R13)
#define CANDSM  2048         // smem candidate table cap (expect ~1050)

typedef unsigned long long u64;
typedef unsigned int u32;
typedef unsigned char uc;

__device__ float4 g_box[NTOT];        // decoded boxes (orig order)
__device__ float  g_kps[NTOT * 10];   // decoded keypoints (orig order)
__device__ u32    g_key32[NTOT];      // sigmoid f32 bits (positive)
__device__ u32    g_perm[NTOT];       // sorted pos -> orig index
__device__ u32    g_cand[NTOT];       // candidate sorted-positions (unordered)
__device__ int    g_nvalid;           // #scores > SCORE_T (sorted prefix len)
__device__ int    g_ncand;            // #candidates (valid & proper box)
__device__ int    g_nedges;
__device__ u32    g_edges[EDGE_CAP];  // (i<<16)|j sorted positions, j<i
__device__ u32    g_done1, g_done2;   // last-block arrival counters (self-reset)

// ---------------------------------------------------------------------------
// K1: decode + zero-fill; last block sorts.
__global__ __launch_bounds__(NTHR1, 1)
void k1_decode_sort(const float* __restrict__ s0, const float* __restrict__ b0, const float* __restrict__ k0,
                    const float* __restrict__ s1, const float* __restrict__ b1, const float* __restrict__ k1,
                    const float* __restrict__ s2, const float* __restrict__ b2, const float* __restrict__ k2,
                    float* __restrict__ out)
{
    extern __shared__ u64 sbitem[];            // [NTOT] bucket-grouped packs
    __shared__ u32 hist[NBUCK], base[NBUCK], cur[NBUCK];
    __shared__ u32 scanbuf[NTHR1];
    __shared__ int nval_s, ncan_s;
    __shared__ u32 arrive_old;

    const int tid = threadIdx.x;
    const int gid = blockIdx.x * NTHR1 + tid;

    // zero-fill whole output (later writes overlay live rows)
    {
        float4 z = make_float4(0.f, 0.f, 0.f, 0.f);
        float4* o4 = (float4*)out;
        for (int q = gid; q < 134400 / 4; q += NBLK * NTHR1) o4[q] = z;
    }

    // ---- decode (one item per thread) ----
    if (gid < NTOT) {
        int n = gid;
        const float *sp, *bp, *kp;
        int local, fw;
        float st;
        if (n < 6400)      { sp = s0; bp = b0; kp = k0; local = n;        fw = 80; st = 8.0f;  }
        else if (n < 8000) { sp = s1; bp = b1; kp = k1; local = n - 6400; fw = 40; st = 16.0f; }
        else               { sp = s2; bp = b2; kp = k2; local = n - 8000; fw = 20; st = 32.0f; }

        float px = (float)(local % fw) * st;   // exact (int * pow2)
        float py = (float)(local / fw) * st;

        // sigmoid in double: correctly-rounded-to-f32 -> monotone ordering
        // (matches JAX ordering; rel_err 4.3e-8 across R7-R13).
        float s = (float)(1.0 / (1.0 + exp(-(double)sp[local])));

        float4 d = ((const float4*)bp)[local]; // pow2 strides -> bit-exact
        float4 bb;
        bb.x = px - d.x * st;
        bb.y = py - d.y * st;
        bb.z = px + d.z * st;
        bb.w = py + d.w * st;
        g_box[n] = bb;

        const float2* kp2 = (const float2*)kp;
#pragma unroll
        for (int q = 0; q < 5; q++) {
            float2 kv = kp2[local * 5 + q];
            g_kps[n * 10 + 2 * q + 0] = px + kv.x * st;
            g_kps[n * 10 + 2 * q + 1] = py + kv.y * st;
        }
        g_key32[n] = __float_as_uint(s);       // positive -> uint order = float order
    }

    // ---- last-block election (spin-free) ----
    __syncthreads();
    __threadfence();                            // release decode stores
    if (tid == 0) arrive_old = atomicAdd(&g_done1, 1u);
    __syncthreads();
    if (arrive_old != NBLK - 1) return;         // not last: exit, no waiting
    __threadfence();                            // acquire side

    // ======== last block: exact stable argsort via counting sort ==========
    // bucket(s) = floor(s*2048): mul by pow2 is exact scaling -> monotone.
    // within-bucket exact rank via strict-total-order pack (key<<14)|(8399-n).
    for (int b = tid; b < NBUCK; b += NTHR1) { hist[b] = 0; cur[b] = 0; }
    if (tid == 0) { nval_s = 0; ncan_s = 0; g_nedges = 0; g_done1 = 0; }
    __syncthreads();

    for (int n = tid; n < NTOT; n += NTHR1) {
        float s = __uint_as_float(g_key32[n]);
        u32 b = (u32)(s * (float)NBUCK);
        if (b > NBUCK - 1) b = NBUCK - 1;
        atomicAdd(&hist[b], 1u);
        if (s > SCORE_T) atomicAdd((u32*)&nval_s, 1u);
    }
    __syncthreads();

    // descending exclusive scan (thread t owns descending slots {2t,2t+1})
    {
        u32 l0 = hist[NBUCK - 1 - (tid * 2)];
        u32 l1 = hist[NBUCK - 1 - (tid * 2 + 1)];
        u32 s2 = l0 + l1;
        scanbuf[tid] = s2;
        __syncthreads();
        for (int off = 1; off < NTHR1; off <<= 1) {
            u32 v = scanbuf[tid];
            u32 add = (tid >= off) ? scanbuf[tid - off] : 0u;
            __syncthreads();
            scanbuf[tid] = v + add;
            __syncthreads();
        }
        u32 run = scanbuf[tid] - s2;
        base[NBUCK - 1 - (tid * 2)]     = run;
        base[NBUCK - 1 - (tid * 2 + 1)] = run + l0;
    }
    __syncthreads();

    // fill bucket lists in smem (slot order irrelevant)
    for (int n = tid; n < NTOT; n += NTHR1) {
        u32 key = g_key32[n];
        float s = __uint_as_float(key);
        u32 b = (u32)(s * (float)NBUCK);
        if (b > NBUCK - 1) b = NBUCK - 1;
        u32 slot = atomicAdd(&cur[b], 1u);
        sbitem[base[b] + slot] = ((u64)key << 14) | (u32)(NTOT - 1 - n);
    }
    __syncthreads();

    // exact within-bucket rank -> perm; candidate compaction
    // candidate = valid (s>T) AND proper (x2>x1 && y2>y1); improper boxes have
    // iou==0 with everything -> participate in no suppression edges.
    for (int n = tid; n < NTOT; n += NTHR1) {
        u32 key = g_key32[n];
        float s = __uint_as_float(key);
        u32 b = (u32)(s * (float)NBUCK);
        if (b > NBUCK - 1) b = NBUCK - 1;
        u32 bs = base[b], L = hist[b];
        u64 me = ((u64)key << 14) | (u32)(NTOT - 1 - n);
        u32 c = 0;
        for (u32 l = 0; l < L; l++)
            c += (sbitem[bs + l] > me) ? 1u : 0u;
        u32 r = bs + c;
        g_perm[r] = n;
        if (s > SCORE_T) {
            float4 bx = g_box[n];
            if (bx.z > bx.x && bx.w > bx.y) {
                int c2 = atomicAdd((u32*)&ncan_s, 1u);
                g_cand[c2] = r;                 // c2 < NTOT always
            }
        }
    }
    __syncthreads();
    if (tid == 0) { g_nvalid = nval_s; g_ncand = ncan_s; }
}

// ---------------------------------------------------------------------------
// K2: edges over smem candidate table + unmasked valid-prefix output;
// last block runs NMS + fixup. IoU replicates JAX bit-for-bit (rn intrinsics).
__global__ __launch_bounds__(NTHR2, 1)
void k2_edge_nms(float* __restrict__ out)
{
    extern __shared__ char sm[];
    // phase 1 overlay: candidate table
    float4* cb = (float4*)sm;                      // [CANDSM]  32KB
    float*  ca = (float*)(sm + CANDSM * 16);       // [CANDSM]   8KB
    u32*    crr = (u32*)(sm + CANDSM * 20);        // [CANDSM]   8KB
    __shared__ u32 arrive_old;
    __shared__ int changed;

    const int tid = threadIdx.x;
    const int nc = g_ncand;
    const int nv = g_nvalid;
    const bool small = (nc <= CANDSM);

    if (small) {
        for (int t = tid; t < nc; t += NTHR2) {
            u32 r = g_cand[t];
            u32 n = g_perm[r];
            float4 bx = g_box[n];
            crr[t] = r;
            cb[t] = bx;
            ca[t] = __fmul_rn(__fsub_rn(bx.z, bx.x), __fsub_rn(bx.w, bx.y));
        }
        __syncthreads();

        for (int a = blockIdx.x; a < nc; a += NBLK) {
            float4 bi = cb[a];
            float  ai = ca[a];
            u32    ri = crr[a];
            for (int b = tid; b < a; b += NTHR2) {
                float4 bj = cb[b];
                float ltx = fmaxf(bi.x, bj.x);
                float lty = fmaxf(bi.y, bj.y);
                float rbx = fminf(bi.z, bj.z);
                float rby = fminf(bi.w, bj.w);
                float w = fmaxf(__fsub_rn(rbx, ltx), 0.0f);
                float h = fmaxf(__fsub_rn(rby, lty), 0.0f);
                float inter = __fmul_rn(w, h);
                if (inter > 0.0f) {
                    float denom = __fadd_rn(__fsub_rn(__fadd_rn(ai, ca[b]), inter), 1e-9f);
                    float iou = __fdiv_rn(inter, denom);
                    if (iou > NMS_T) {
                        u32 rj = crr[b];
                        u32 hi = ri > rj ? ri : rj;
                        u32 lo = ri > rj ? rj : ri;
                        int pos = atomicAdd(&g_nedges, 1);
                        if (pos < EDGE_CAP) g_edges[pos] = (hi << 16) | lo;
                    }
                }
            }
        }
    } else {
        // fallback: row-wise over valid prefix via perm gathers (any data)
        for (int i = 1 + blockIdx.x; i < nv; i += NBLK) {
            float4 bi = g_box[g_perm[i]];
            if (!(bi.z > bi.x && bi.w > bi.y)) continue;
            float ai = __fmul_rn(__fsub_rn(bi.z, bi.x), __fsub_rn(bi.w, bi.y));
            for (int j = tid; j < i; j += NTHR2) {
                float4 bj = g_box[g_perm[j]];
                float ltx = fmaxf(bi.x, bj.x);
                float lty = fmaxf(bi.y, bj.y);
                float rbx = fminf(bi.z, bj.z);
                float rby = fminf(bi.w, bj.w);
                float w = fmaxf(__fsub_rn(rbx, ltx), 0.0f);
                float h = fmaxf(__fsub_rn(rby, lty), 0.0f);
                float inter = __fmul_rn(w, h);
                if (inter > 0.0f) {
                    float aj = __fmul_rn(__fsub_rn(bj.z, bj.x), __fsub_rn(bj.w, bj.y));
                    float denom = __fadd_rn(__fsub_rn(__fadd_rn(ai, aj), inter), 1e-9f);
                    float iou = __fdiv_rn(inter, denom);
                    if (iou > NMS_T) {
                        int pos = atomicAdd(&g_nedges, 1);
                        if (pos < EDGE_CAP) g_edges[pos] = ((u32)i << 16) | (u32)j;
                    }
                }
            }
        }
    }

    // unmasked outputs for valid prefix (rest of out already zero from K1)
    for (int p = blockIdx.x * NTHR2 + tid; p < nv; p += NBLK * NTHR2) {
        u32 n = g_perm[p];
        float4 b = g_box[n];
        out[p * 4 + 0] = b.x;
        out[p * 4 + 1] = b.y;
        out[p * 4 + 2] = b.z;
        out[p * 4 + 3] = b.w;
        out[33600 + p] = __uint_as_float(g_key32[n]);
#pragma unroll
        for (int q = 0; q < 10; q++)
            out[42000 + p * 10 + q] = g_kps[n * 10 + q];
    }

    // ---- last-block election (spin-free) ----
    __syncthreads();
    __threadfence();                            // release edges + output stores
    if (tid == 0) arrive_old = atomicAdd(&g_done2, 1u);
    __syncthreads();
    if (arrive_old != NBLK - 1) return;
    __threadfence();                            // acquire side

    // ======== last block: NMS fixpoint (reuse smem) ========================
    // keep[i] = valid[i] && !any((i,j) edge: keep[j]); unique fixpoint on the
    // j<i DAG; Jacobi iterate, "no change" = exact; NTOT+1 cap = hard bound.
    {
        u32* es   = (u32*)sm;                   // [ESMEM]  64KB
        uc*  keep = (uc*)(es + ESMEM);          // [NTOT]
        uc*  sup  = keep + NTOT;                // [NTOT]

        int ne = g_nedges;
        if (ne > EDGE_CAP) ne = EDGE_CAP;
        bool use_s = (ne <= ESMEM);
        __syncthreads();                        // done with candidate table
        if (use_s)
            for (int e = tid; e < ne; e += NTHR2) es[e] = g_edges[e];
        for (int p = tid; p < NTOT; p += NTHR2)
            keep[p] = (p < nv) ? 1 : 0;         // valid prefix
        __syncthreads();
        const u32* E = use_s ? es : g_edges;

        for (int it = 0; it < NTOT + 1; it++) {
            if (tid == 0) changed = 0;
            for (int e = tid; e < ne; e += NTHR2) sup[E[e] >> 16] = 0;
            __syncthreads();
            for (int e = tid; e < ne; e += NTHR2) {
                u32 x = E[e];
                if (keep[x & 0xffffu]) sup[x >> 16] = 1;
            }
            __syncthreads();
            for (int e = tid; e < ne; e += NTHR2) {
                int i = (int)(E[e] >> 16);
                uc nz = (!sup[i]) ? 1 : 0;      // i < nv by construction
                if (keep[i] != nz) { keep[i] = nz; changed = 1; }
            }
            __syncthreads();
            int ch = changed;
            __syncthreads();
            if (!ch) break;
        }

        // fixup: kept rows -> keep=1; suppressed valid rows -> re-zero.
        for (int p = tid; p < nv; p += NTHR2) {
            if (keep[p]) {
                out[126000 + p] = 1.0f;
            } else {
                out[p * 4 + 0] = 0.0f;
                out[p * 4 + 1] = 0.0f;
                out[p * 4 + 2] = 0.0f;
                out[p * 4 + 3] = 0.0f;
                out[33600 + p] = 0.0f;
#pragma unroll
                for (int q = 0; q < 10; q++)
                    out[42000 + p * 10 + q] = 0.0f;
            }
        }
        __syncthreads();
        if (tid == 0) g_done2 = 0;              // all arrivals observed; safe
    }
}

// ---------------------------------------------------------------------------
extern "C" void kernel_launch(void* const* d_in, const int* in_sizes, int n_in,
                              void* d_out, int out_size)
{
    const float *s0, *b0, *k0, *s1, *b1, *k1, *s2, *b2, *k2;
    // dict-insertion order (score0,bbox0,kps0,...) vs signature order
    if (n_in >= 9 && in_sizes[1] == 25600) {
        s0 = (const float*)d_in[0]; b0 = (const float*)d_in[1]; k0 = (const float*)d_in[2];
        s1 = (const float*)d_in[3]; b1 = (const float*)d_in[4]; k1 = (const float*)d_in[5];
        s2 = (const float*)d_in[6]; b2 = (const float*)d_in[7]; k2 = (const float*)d_in[8];
    } else {
        s0 = (const float*)d_in[0]; s1 = (const float*)d_in[1]; s2 = (const float*)d_in[2];
        b0 = (const float*)d_in[3]; b1 = (const float*)d_in[4]; b2 = (const float*)d_in[5];
        k0 = (const float*)d_in[6]; k1 = (const float*)d_in[7]; k2 = (const float*)d_in[8];
    }

    const int k1_smem = NTOT * 8;                        // 67,200 B (bitem)
    const int k2_smem = ESMEM * 4 + 2 * NTOT;            // 82,336 B (nms > cand)
    cudaFuncSetAttribute(k1_decode_sort, cudaFuncAttributeMaxDynamicSharedMemorySize, k1_smem);
    cudaFuncSetAttribute(k2_edge_nms,    cudaFuncAttributeMaxDynamicSharedMemorySize, k2_smem);

    k1_decode_sort<<<NBLK, NTHR1, k1_smem>>>(s0, b0, k0, s1, b1, k1, s2, b2, k2, (float*)d_out);
    k2_edge_nms<<<NBLK, NTHR2, k2_smem>>>((float*)d_out);
}

// round 15
// speedup vs baseline: 2.1292x; 1.0794x over previous
#include <cuda_runtime.h>
#include <math.h>

// ---------------------------------------------------------------------------
// SCRFD post-processing in TWO graph nodes (spin-free last-block pattern):
//   K1: decode + zero-fill out (all blocks); LAST block: counting-sort argsort
//       (exact, stable) -> g_perm, pre-compacted candidate table, resets
//   K2: candidate pair sweep (warp-aggregated edge emit) + unmasked output
//       (all blocks); LAST block: smem Jacobi NMS + suppressed-row fixup
//
// Output layout (float32, 134400 elems):
//   [0:33600) boxes[8400,4] | [33600:42000) scores | [42000:126000) kps[8400,10]
//   | [126000:134400) keep
// ---------------------------------------------------------------------------

#define NTOT    8400
#define NBLK    132
#define NTHR    1024
#define NBUCK   2048
#define SCORE_T 0.5f
#define NMS_T   0.4f
#define EDGE_CAP (1 << 22)
#define ESMEM   16384        // smem edge cache (ne bracketed <=16384 in R9/R13)
#define CANDSM  2048         // smem candidate table cap (expect ~1050)
#define FULLM   0xffffffffu

typedef unsigned long long u64;
typedef unsigned int u32;
typedef unsigned char uc;

__device__ float4 g_box[NTOT];        // decoded boxes (orig order)
__device__ float  g_kps[NTOT * 10];   // decoded keypoints (orig order)
__device__ u32    g_key32[NTOT];      // sigmoid f32 bits (positive)
__device__ u32    g_perm[NTOT];       // sorted pos -> orig index
__device__ float4 g_cbox[NTOT];       // compacted candidate boxes
__device__ float  g_carea[NTOT];      // compacted candidate areas
__device__ u32    g_crank[NTOT];      // compacted candidate sorted-positions
__device__ int    g_nvalid;           // #scores > SCORE_T (sorted prefix len)
__device__ int    g_ncand;            // #candidates (valid & proper box)
__device__ int    g_nedges;
__device__ u32    g_edges[EDGE_CAP];  // (i<<16)|j sorted positions, j<i
__device__ u32    g_done1, g_done2;   // last-block arrival counters (self-reset)

// ---------------------------------------------------------------------------
// K1: decode + zero-fill; last block sorts + compacts candidates.
__global__ __launch_bounds__(NTHR, 1)
void k1_decode_sort(const float* __restrict__ s0, const float* __restrict__ b0, const float* __restrict__ k0,
                    const float* __restrict__ s1, const float* __restrict__ b1, const float* __restrict__ k1,
                    const float* __restrict__ s2, const float* __restrict__ b2, const float* __restrict__ k2,
                    float* __restrict__ out)
{
    extern __shared__ u64 sbitem[];            // [NTOT] bucket-grouped packs
    __shared__ u32 hist[NBUCK], base[NBUCK], cur[NBUCK];
    __shared__ u32 scanbuf[NTHR];
    __shared__ int nval_s, ncan_s;
    __shared__ u32 arrive_old;

    const int tid = threadIdx.x;
    const int lane = tid & 31;
    const int gid = blockIdx.x * NTHR + tid;

    // zero-fill whole output (later writes overlay live rows)
    {
        float4 z = make_float4(0.f, 0.f, 0.f, 0.f);
        float4* o4 = (float4*)out;
        for (int q = gid; q < 134400 / 4; q += NBLK * NTHR) o4[q] = z;
    }

    // ---- decode (one item per thread) ----
    if (gid < NTOT) {
        int n = gid;
        const float *sp, *bp, *kp;
        int local, fw;
        float st;
        if (n < 6400)      { sp = s0; bp = b0; kp = k0; local = n;        fw = 80; st = 8.0f;  }
        else if (n < 8000) { sp = s1; bp = b1; kp = k1; local = n - 6400; fw = 40; st = 16.0f; }
        else               { sp = s2; bp = b2; kp = k2; local = n - 8000; fw = 20; st = 32.0f; }

        float px = (float)(local % fw) * st;   // exact (int * pow2)
        float py = (float)(local / fw) * st;

        // sigmoid in double: correctly-rounded-to-f32 -> monotone ordering
        // (matches JAX ordering; rel_err 4.3e-8 across R7-R14).
        float s = (float)(1.0 / (1.0 + exp(-(double)sp[local])));

        float4 d = ((const float4*)bp)[local]; // pow2 strides -> bit-exact
        float4 bb;
        bb.x = px - d.x * st;
        bb.y = py - d.y * st;
        bb.z = px + d.z * st;
        bb.w = py + d.w * st;
        g_box[n] = bb;

        const float2* kp2 = (const float2*)kp;
        float2* ko = (float2*)g_kps;
#pragma unroll
        for (int q = 0; q < 5; q++) {
            float2 kv = kp2[local * 5 + q];
            float2 kd;
            kd.x = px + kv.x * st;
            kd.y = py + kv.y * st;
            ko[n * 5 + q] = kd;
        }
        g_key32[n] = __float_as_uint(s);       // positive -> uint order = float order
    }

    // ---- last-block election (spin-free) ----
    __syncthreads();
    __threadfence();                            // release decode stores
    if (tid == 0) arrive_old = atomicAdd(&g_done1, 1u);
    __syncthreads();
    if (arrive_old != NBLK - 1) return;         // not last: exit, no waiting
    __threadfence();                            // acquire side

    // ======== last block: exact stable argsort via counting sort ==========
    // bucket(s) = floor(s*2048): mul by pow2 is exact scaling -> monotone.
    // within-bucket exact rank via strict-total-order pack (key<<14)|(8399-n).
    for (int b = tid; b < NBUCK; b += NTHR) { hist[b] = 0; cur[b] = 0; }
    if (tid == 0) { nval_s = 0; ncan_s = 0; g_nedges = 0; g_done1 = 0; }
    __syncthreads();

    // histogram + ballot-aggregated valid count
    for (int n0 = 0; n0 < NTOT; n0 += NTHR) {
        int n = n0 + tid;
        bool in = (n < NTOT);
        u32 key = in ? g_key32[n] : 0u;
        float s = __uint_as_float(key);
        if (in) {
            u32 b = (u32)(s * (float)NBUCK);
            if (b > NBUCK - 1) b = NBUCK - 1;
            atomicAdd(&hist[b], 1u);
        }
        unsigned m = __ballot_sync(FULLM, in && (s > SCORE_T));
        if (lane == 0 && m) atomicAdd((u32*)&nval_s, (u32)__popc(m));
    }
    __syncthreads();

    // descending exclusive scan (thread t owns descending slots {2t,2t+1})
    {
        u32 l0 = hist[NBUCK - 1 - (tid * 2)];
        u32 l1 = hist[NBUCK - 1 - (tid * 2 + 1)];
        u32 s2 = l0 + l1;
        scanbuf[tid] = s2;
        __syncthreads();
        for (int off = 1; off < NTHR; off <<= 1) {
            u32 v = scanbuf[tid];
            u32 add = (tid >= off) ? scanbuf[tid - off] : 0u;
            __syncthreads();
            scanbuf[tid] = v + add;
            __syncthreads();
        }
        u32 run = scanbuf[tid] - s2;
        base[NBUCK - 1 - (tid * 2)]     = run;
        base[NBUCK - 1 - (tid * 2 + 1)] = run + l0;
    }
    __syncthreads();

    // fill bucket lists in smem (slot order irrelevant)
    for (int n = tid; n < NTOT; n += NTHR) {
        u32 key = g_key32[n];
        float s = __uint_as_float(key);
        u32 b = (u32)(s * (float)NBUCK);
        if (b > NBUCK - 1) b = NBUCK - 1;
        u32 slot = atomicAdd(&cur[b], 1u);
        sbitem[base[b] + slot] = ((u64)key << 14) | (u32)(NTOT - 1 - n);
    }
    __syncthreads();

    // exact within-bucket rank -> perm; candidate compaction (ballot-agg).
    // candidate = valid (s>T) AND proper (x2>x1 && y2>y1); improper boxes
    // have iou==0 with everything -> participate in no suppression edges.
    for (int n0 = 0; n0 < NTOT; n0 += NTHR) {
        int n = n0 + tid;
        bool in = (n < NTOT);
        bool pred = false;
        float4 bx;
        float area = 0.0f;
        u32 r = 0;
        if (in) {
            u32 key = g_key32[n];
            float s = __uint_as_float(key);
            u32 b = (u32)(s * (float)NBUCK);
            if (b > NBUCK - 1) b = NBUCK - 1;
            u32 bs = base[b], L = hist[b];
            u64 me = ((u64)key << 14) | (u32)(NTOT - 1 - n);
            u32 c = 0;
            for (u32 l = 0; l < L; l++)
                c += (sbitem[bs + l] > me) ? 1u : 0u;
            r = bs + c;
            g_perm[r] = (u32)n;
            if (s > SCORE_T) {
                bx = g_box[n];
                if (bx.z > bx.x && bx.w > bx.y) {
                    pred = true;
                    area = __fmul_rn(__fsub_rn(bx.z, bx.x), __fsub_rn(bx.w, bx.y));
                }
            }
        }
        unsigned m = __ballot_sync(FULLM, pred);
        if (pred) {
            int leader = __ffs(m) - 1;
            u32 bpos;
            if (lane == leader) bpos = atomicAdd((u32*)&ncan_s, (u32)__popc(m));
            bpos = __shfl_sync(m, bpos, leader);
            u32 slot = bpos + (u32)__popc(m & ((1u << lane) - 1u));
            g_cbox[slot]  = bx;
            g_carea[slot] = area;
            g_crank[slot] = r;
        }
    }
    __syncthreads();
    if (tid == 0) { g_nvalid = nval_s; g_ncand = ncan_s; }
}

// ---------------------------------------------------------------------------
// K2: edges over smem candidate table (warp-aggregated emit) + unmasked
// valid-prefix output; last block runs NMS + fixup.
// IoU replicates JAX bit-for-bit (rn intrinsics block FMA contraction).
__global__ __launch_bounds__(NTHR, 1)
void k2_edge_nms(float* __restrict__ out)
{
    extern __shared__ char sm[];
    float4* cb = (float4*)sm;                      // [CANDSM]  32KB
    float*  ca = (float*)(sm + CANDSM * 16);       // [CANDSM]   8KB
    u32*    cr = (u32*)(sm + CANDSM * 20);         // [CANDSM]   8KB
    __shared__ u32 arrive_old;
    __shared__ int changed;

    const int tid = threadIdx.x;
    const int lane = tid & 31;
    const int nc = g_ncand;
    const int nv = g_nvalid;
    const bool small = (nc <= CANDSM);

    if (small) {
        for (int t = tid; t < nc; t += NTHR) {     // independent linear streams
            cb[t] = g_cbox[t];
            ca[t] = g_carea[t];
            cr[t] = g_crank[t];
        }
        __syncthreads();

        for (int a = blockIdx.x; a < nc; a += NBLK) {
            float4 bi = cb[a];
            float  ai = ca[a];
            u32    ri = cr[a];
            for (int b0 = 0; b0 < a; b0 += NTHR) { // warp-uniform iterations
                int b = b0 + tid;
                bool in = (b < a);
                bool pred = false;
                u32 pk = 0;
                if (in) {
                    float4 bj = cb[b];
                    float ltx = fmaxf(bi.x, bj.x);
                    float lty = fmaxf(bi.y, bj.y);
                    float rbx = fminf(bi.z, bj.z);
                    float rby = fminf(bi.w, bj.w);
                    float w = fmaxf(__fsub_rn(rbx, ltx), 0.0f);
                    float h = fmaxf(__fsub_rn(rby, lty), 0.0f);
                    float inter = __fmul_rn(w, h);
                    if (inter > 0.0f) {
                        float denom = __fadd_rn(__fsub_rn(__fadd_rn(ai, ca[b]), inter), 1e-9f);
                        float iou = __fdiv_rn(inter, denom);
                        if (iou > NMS_T) {
                            u32 rj = cr[b];
                            u32 hi = ri > rj ? ri : rj;
                            u32 lo = ri > rj ? rj : ri;
                            pk = (hi << 16) | lo;
                            pred = true;
                        }
                    }
                }
                unsigned m = __ballot_sync(FULLM, pred);   // warp-aggregated emit
                if (pred) {
                    int leader = __ffs(m) - 1;
                    int bpos;
                    if (lane == leader) bpos = atomicAdd(&g_nedges, __popc(m));
                    bpos = __shfl_sync(m, bpos, leader);
                    int slot = bpos + __popc(m & ((1u << lane) - 1u));
                    if (slot < EDGE_CAP) g_edges[slot] = pk;
                }
            }
        }
    } else {
        // fallback (cold): row-wise over valid prefix via perm gathers
        for (int i = 1 + blockIdx.x; i < nv; i += NBLK) {
            float4 bi = g_box[g_perm[i]];
            if (!(bi.z > bi.x && bi.w > bi.y)) continue;
            float ai = __fmul_rn(__fsub_rn(bi.z, bi.x), __fsub_rn(bi.w, bi.y));
            for (int j = tid; j < i; j += NTHR) {
                float4 bj = g_box[g_perm[j]];
                float ltx = fmaxf(bi.x, bj.x);
                float lty = fmaxf(bi.y, bj.y);
                float rbx = fminf(bi.z, bj.z);
                float rby = fminf(bi.w, bj.w);
                float w = fmaxf(__fsub_rn(rbx, ltx), 0.0f);
                float h = fmaxf(__fsub_rn(rby, lty), 0.0f);
                float inter = __fmul_rn(w, h);
                if (inter > 0.0f) {
                    float aj = __fmul_rn(__fsub_rn(bj.z, bj.x), __fsub_rn(bj.w, bj.y));
                    float denom = __fadd_rn(__fsub_rn(__fadd_rn(ai, aj), inter), 1e-9f);
                    float iou = __fdiv_rn(inter, denom);
                    if (iou > NMS_T) {
                        int pos = atomicAdd(&g_nedges, 1);
                        if (pos < EDGE_CAP) g_edges[pos] = ((u32)i << 16) | (u32)j;
                    }
                }
            }
        }
    }

    // unmasked outputs for valid prefix (rest of out already zero from K1)
    {
        float4* ob = (float4*)out;
        float2* ok = (float2*)(out + 42000);
        const float2* ik = (const float2*)g_kps;
        for (int p = blockIdx.x * NTHR + tid; p < nv; p += NBLK * NTHR) {
            u32 n = g_perm[p];
            ob[p] = g_box[n];
            out[33600 + p] = __uint_as_float(g_key32[n]);
#pragma unroll
            for (int q = 0; q < 5; q++)
                ok[p * 5 + q] = ik[n * 5 + q];
        }
    }

    // ---- last-block election (spin-free) ----
    __syncthreads();
    __threadfence();                            // release edges + output stores
    if (tid == 0) arrive_old = atomicAdd(&g_done2, 1u);
    __syncthreads();
    if (arrive_old != NBLK - 1) return;
    __threadfence();                            // acquire side

    // ======== last block: NMS fixpoint (reuse smem) ========================
    // keep[i] = valid[i] && !any((i,j) edge: keep[j]); unique fixpoint on the
    // j<i DAG; Jacobi iterate, "no change" = exact; NTOT+1 cap = hard bound.
    {
        u32* es   = (u32*)sm;                   // [ESMEM]  64KB
        uc*  keep = (uc*)(es + ESMEM);          // [NTOT]
        uc*  sup  = keep + NTOT;                // [NTOT]

        int ne = g_nedges;
        if (ne > EDGE_CAP) ne = EDGE_CAP;
        bool use_s = (ne <= ESMEM);
        __syncthreads();                        // done with candidate table
        if (use_s)
            for (int e = tid; e < ne; e += NTHR) es[e] = g_edges[e];
        for (int p = tid; p < NTOT; p += NTHR)
            keep[p] = (p < nv) ? 1 : 0;         // valid prefix
        __syncthreads();
        const u32* E = use_s ? es : g_edges;

        for (int it = 0; it < NTOT + 1; it++) {
            if (tid == 0) changed = 0;
            for (int e = tid; e < ne; e += NTHR) sup[E[e] >> 16] = 0;
            __syncthreads();
            for (int e = tid; e < ne; e += NTHR) {
                u32 x = E[e];
                if (keep[x & 0xffffu]) sup[x >> 16] = 1;
            }
            __syncthreads();
            for (int e = tid; e < ne; e += NTHR) {
                int i = (int)(E[e] >> 16);
                uc nz = (!sup[i]) ? 1 : 0;      // i < nv by construction
                if (keep[i] != nz) { keep[i] = nz; changed = 1; }
            }
            __syncthreads();
            int ch = changed;
            __syncthreads();
            if (!ch) break;
        }

        // fixup: kept rows -> keep=1; suppressed valid rows -> re-zero.
        float4* ob = (float4*)out;
        float2* ok = (float2*)(out + 42000);
        for (int p = tid; p < nv; p += NTHR) {
            if (keep[p]) {
                out[126000 + p] = 1.0f;
            } else {
                ob[p] = make_float4(0.f, 0.f, 0.f, 0.f);
                out[33600 + p] = 0.0f;
                float2 z2 = make_float2(0.f, 0.f);
#pragma unroll
                for (int q = 0; q < 5; q++)
                    ok[p * 5 + q] = z2;
            }
        }
        __syncthreads();
        if (tid == 0) g_done2 = 0;              // all arrivals observed; safe
    }
}

// ---------------------------------------------------------------------------
extern "C" void kernel_launch(void* const* d_in, const int* in_sizes, int n_in,
                              void* d_out, int out_size)
{
    const float *s0, *b0, *k0, *s1, *b1, *k1, *s2, *b2, *k2;
    // dict-insertion order (score0,bbox0,kps0,...) vs signature order
    if (n_in >= 9 && in_sizes[1] == 25600) {
        s0 = (const float*)d_in[0]; b0 = (const float*)d_in[1]; k0 = (const float*)d_in[2];
        s1 = (const float*)d_in[3]; b1 = (const float*)d_in[4]; k1 = (const float*)d_in[5];
        s2 = (const float*)d_in[6]; b2 = (const float*)d_in[7]; k2 = (const float*)d_in[8];
    } else {
        s0 = (const float*)d_in[0]; s1 = (const float*)d_in[1]; s2 = (const float*)d_in[2];
        b0 = (const float*)d_in[3]; b1 = (const float*)d_in[4]; b2 = (const float*)d_in[5];
        k0 = (const float*)d_in[6]; k1 = (const float*)d_in[7]; k2 = (const float*)d_in[8];
    }

    const int k1_smem = NTOT * 8;                        // 67,200 B (bitem)
    const int k2_smem = ESMEM * 4 + 2 * NTOT;            // 82,336 B (nms > cand)
    cudaFuncSetAttribute(k1_decode_sort, cudaFuncAttributeMaxDynamicSharedMemorySize, k1_smem);
    cudaFuncSetAttribute(k2_edge_nms,    cudaFuncAttributeMaxDynamicSharedMemorySize, k2_smem);

    k1_decode_sort<<<NBLK, NTHR, k1_smem>>>(s0, b0, k0, s1, b1, k1, s2, b2, k2, (float*)d_out);
    k2_edge_nms<<<NBLK, NTHR, k2_smem>>>((float*)d_out);
}

// round 16
// speedup vs baseline: 2.3269x; 1.0929x over previous
#include <cuda_runtime.h>
#include <math.h>

// ---------------------------------------------------------------------------
// SCRFD post-processing in TWO graph nodes (spin-free last-block pattern):
//   K1: decode spread over ALL SMs (64 items/block; the fp64 sigmoid is the
//       per-SM cost) ; LAST block: counting-sort argsort (exact, stable)
//       -> g_perm + pre-compacted candidate table + counter resets
//   K2: candidate pair sweep (warp-aggregated edge emit) + unmasked output
//       + invalid-row zeroing (all blocks); LAST block: smem ping-pong Jacobi
//       NMS + suppressed-row fixup
//
// Output layout (float32, 134400 elems):
//   [0:33600) boxes[8400,4] | [33600:42000) scores | [42000:126000) kps[8400,10]
//   | [126000:134400) keep
// ---------------------------------------------------------------------------

#define NTOT    8400
#define NBLK    132
#define NTHR    1024
#define NBUCK   2048
#define SCORE_T 0.5f
#define NMS_T   0.4f
#define EDGE_CAP (1 << 22)
#define ESMEM   16384        // smem edge cache (ne bracketed <=16384 in R9/R13)
#define CANDSM  2048         // smem candidate table cap (expect ~1050)
#define FULLM   0xffffffffu

typedef unsigned long long u64;
typedef unsigned int u32;
typedef unsigned char uc;

__device__ float4 g_box[NTOT];        // decoded boxes (orig order)
__device__ float  g_kps[NTOT * 10];   // decoded keypoints (orig order)
__device__ u32    g_key32[NTOT];      // sigmoid f32 bits (positive)
__device__ u32    g_perm[NTOT];       // sorted pos -> orig index
__device__ float4 g_cbox[NTOT];       // compacted candidate boxes
__device__ float  g_carea[NTOT];      // compacted candidate areas
__device__ u32    g_crank[NTOT];      // compacted candidate sorted-positions
__device__ int    g_nvalid;           // #scores > SCORE_T (sorted prefix len)
__device__ int    g_ncand;            // #candidates (valid & proper box)
__device__ int    g_nedges;
__device__ u32    g_edges[EDGE_CAP];  // (i<<16)|j sorted positions, j<i
__device__ u32    g_done1, g_done2;   // last-block arrival counters (self-reset)

// ---------------------------------------------------------------------------
// K1: decode (64 items per block -> DP sigmoid spread over all SMs);
//     last block: counting-sort argsort + candidate compaction.
__global__ __launch_bounds__(NTHR, 1)
void k1_decode_sort(const float* __restrict__ s0, const float* __restrict__ b0, const float* __restrict__ k0,
                    const float* __restrict__ s1, const float* __restrict__ b1, const float* __restrict__ k1,
                    const float* __restrict__ s2, const float* __restrict__ b2, const float* __restrict__ k2)
{
    extern __shared__ char dsm[];
    u64* sbitem = (u64*)dsm;                   // [NTOT] bucket-grouped packs
    u32* skey   = (u32*)(dsm + NTOT * 8);      // [NTOT] key cache
    __shared__ u32 hist[NBUCK], base[NBUCK], cur[NBUCK];
    __shared__ u32 wsum[32];
    __shared__ int nval_s, ncan_s;
    __shared__ u32 arrive_old;

    const int tid = threadIdx.x;
    const int lane = tid & 31;
    const int wid = tid >> 5;

    // ---- decode: block b handles items [b*64, b*64+64) ----
    {
        int n = blockIdx.x * 64 + tid;
        if (tid < 64 && n < NTOT) {
            const float *sp, *bp, *kp;
            int local, fw;
            float st;
            if (n < 6400)      { sp = s0; bp = b0; kp = k0; local = n;        fw = 80; st = 8.0f;  }
            else if (n < 8000) { sp = s1; bp = b1; kp = k1; local = n - 6400; fw = 40; st = 16.0f; }
            else               { sp = s2; bp = b2; kp = k2; local = n - 8000; fw = 20; st = 32.0f; }

            float px = (float)(local % fw) * st;   // exact (int * pow2)
            float py = (float)(local / fw) * st;

            // sigmoid in double: correctly-rounded-to-f32 -> monotone ordering
            // (matches JAX ordering; rel_err 4.3e-8 across R7-R15).
            float s = (float)(1.0 / (1.0 + exp(-(double)sp[local])));

            float4 d = ((const float4*)bp)[local]; // pow2 strides -> bit-exact
            float4 bb;
            bb.x = px - d.x * st;
            bb.y = py - d.y * st;
            bb.z = px + d.z * st;
            bb.w = py + d.w * st;
            g_box[n] = bb;

            const float2* kp2 = (const float2*)kp;
            float2* ko = (float2*)g_kps;
#pragma unroll
            for (int q = 0; q < 5; q++) {
                float2 kv = kp2[local * 5 + q];
                float2 kd;
                kd.x = px + kv.x * st;
                kd.y = py + kv.y * st;
                ko[n * 5 + q] = kd;
            }
            g_key32[n] = __float_as_uint(s);   // positive -> uint order = float order
        }
    }

    // ---- last-block election (spin-free) ----
    __syncthreads();
    __threadfence();                            // release decode stores
    if (tid == 0) arrive_old = atomicAdd(&g_done1, 1u);
    __syncthreads();
    if (arrive_old != NBLK - 1) return;         // not last: exit, no waiting
    __threadfence();                            // acquire side

    // ======== last block: exact stable argsort via counting sort ==========
    // bucket(s) = floor(s*2048): mul by pow2 is exact scaling -> monotone.
    // within-bucket exact rank via strict-total-order pack (key<<14)|(8399-n).
    for (int b = tid; b < NBUCK; b += NTHR) { hist[b] = 0; cur[b] = 0; }
    if (tid == 0) { nval_s = 0; ncan_s = 0; g_nedges = 0; g_done1 = 0; }
    __syncthreads();

    // load keys into smem + histogram + ballot-aggregated valid count
    for (int n0 = 0; n0 < NTOT; n0 += NTHR) {
        int n = n0 + tid;
        bool in = (n < NTOT);
        u32 key = in ? g_key32[n] : 0u;
        float s = __uint_as_float(key);
        if (in) {
            skey[n] = key;
            u32 b = (u32)(s * (float)NBUCK);
            if (b > NBUCK - 1) b = NBUCK - 1;
            atomicAdd(&hist[b], 1u);
        }
        unsigned m = __ballot_sync(FULLM, in && (s > SCORE_T));
        if (lane == 0 && m) atomicAdd((u32*)&nval_s, (u32)__popc(m));
    }
    __syncthreads();

    // descending exclusive scan via warp shuffles (thread t owns desc {2t,2t+1})
    {
        u32 l0 = hist[NBUCK - 1 - (tid * 2)];
        u32 l1 = hist[NBUCK - 1 - (tid * 2 + 1)];
        u32 s2 = l0 + l1;
        u32 v = s2;
#pragma unroll
        for (int off = 1; off < 32; off <<= 1) {
            u32 t = __shfl_up_sync(FULLM, v, off);
            if (lane >= off) v += t;
        }
        if (lane == 31) wsum[wid] = v;
        __syncthreads();
        if (wid == 0) {
            u32 w = wsum[lane];
            u32 vv = w;
#pragma unroll
            for (int off = 1; off < 32; off <<= 1) {
                u32 t = __shfl_up_sync(FULLM, vv, off);
                if (lane >= off) vv += t;
            }
            wsum[lane] = vv - w;                // exclusive warp base
        }
        __syncthreads();
        u32 excl = wsum[wid] + (v - s2);
        base[NBUCK - 1 - (tid * 2)]     = excl;
        base[NBUCK - 1 - (tid * 2 + 1)] = excl + l0;
    }
    __syncthreads();

    // fill bucket lists in smem (slot order irrelevant)
    for (int n = tid; n < NTOT; n += NTHR) {
        u32 key = skey[n];
        float s = __uint_as_float(key);
        u32 b = (u32)(s * (float)NBUCK);
        if (b > NBUCK - 1) b = NBUCK - 1;
        u32 slot = atomicAdd(&cur[b], 1u);
        sbitem[base[b] + slot] = ((u64)key << 14) | (u32)(NTOT - 1 - n);
    }
    __syncthreads();

    // exact within-bucket rank -> perm; candidate compaction (ballot-agg).
    // candidate = valid (s>T) AND proper (x2>x1 && y2>y1); improper boxes
    // have iou==0 with everything -> participate in no suppression edges.
    for (int n0 = 0; n0 < NTOT; n0 += NTHR) {
        int n = n0 + tid;
        bool in = (n < NTOT);
        bool pred = false;
        float4 bx;
        float area = 0.0f;
        u32 r = 0;
        if (in) {
            u32 key = skey[n];
            float s = __uint_as_float(key);
            u32 b = (u32)(s * (float)NBUCK);
            if (b > NBUCK - 1) b = NBUCK - 1;
            u32 bs = base[b], L = hist[b];
            u64 me = ((u64)key << 14) | (u32)(NTOT - 1 - n);
            u32 c = 0;
            for (u32 l = 0; l < L; l++)
                c += (sbitem[bs + l] > me) ? 1u : 0u;
            r = bs + c;
            g_perm[r] = (u32)n;
            if (s > SCORE_T) {
                bx = g_box[n];
                if (bx.z > bx.x && bx.w > bx.y) {
                    pred = true;
                    area = __fmul_rn(__fsub_rn(bx.z, bx.x), __fsub_rn(bx.w, bx.y));
                }
            }
        }
        unsigned m = __ballot_sync(FULLM, pred);
        if (pred) {
            int leader = __ffs(m) - 1;
            u32 bpos;
            if (lane == leader) bpos = atomicAdd((u32*)&ncan_s, (u32)__popc(m));
            bpos = __shfl_sync(m, bpos, leader);
            u32 slot = bpos + (u32)__popc(m & ((1u << lane) - 1u));
            g_cbox[slot]  = bx;
            g_carea[slot] = area;
            g_crank[slot] = r;
        }
    }
    __syncthreads();
    if (tid == 0) { g_nvalid = nval_s; g_ncand = ncan_s; }
}

// ---------------------------------------------------------------------------
// K2: edges over smem candidate table (warp-aggregated emit) + unmasked
// valid-prefix output + invalid-row/keep zeroing; last block: ping-pong
// Jacobi NMS + fixup. IoU replicates JAX bit-for-bit (rn intrinsics).
__global__ __launch_bounds__(NTHR, 1)
void k2_edge_nms(float* __restrict__ out)
{
    extern __shared__ char sm[];
    float4* cb = (float4*)sm;                      // [CANDSM]  32KB
    float*  ca = (float*)(sm + CANDSM * 16);       // [CANDSM]   8KB
    u32*    cr = (u32*)(sm + CANDSM * 20);         // [CANDSM]   8KB
    __shared__ u32 arrive_old;
    __shared__ int changed;

    const int tid = threadIdx.x;
    const int lane = tid & 31;
    const int nc = g_ncand;
    const int nv = g_nvalid;
    const bool small = (nc <= CANDSM);

    if (small) {
        for (int t = tid; t < nc; t += NTHR) {     // independent linear streams
            cb[t] = g_cbox[t];
            ca[t] = g_carea[t];
            cr[t] = g_crank[t];
        }
        __syncthreads();

        for (int a = blockIdx.x; a < nc; a += NBLK) {
            float4 bi = cb[a];
            float  ai = ca[a];
            u32    ri = cr[a];
            for (int b0 = 0; b0 < a; b0 += NTHR) { // warp-uniform iterations
                int b = b0 + tid;
                bool in = (b < a);
                bool pred = false;
                u32 pk = 0;
                if (in) {
                    float4 bj = cb[b];
                    float ltx = fmaxf(bi.x, bj.x);
                    float lty = fmaxf(bi.y, bj.y);
                    float rbx = fminf(bi.z, bj.z);
                    float rby = fminf(bi.w, bj.w);
                    float w = fmaxf(__fsub_rn(rbx, ltx), 0.0f);
                    float h = fmaxf(__fsub_rn(rby, lty), 0.0f);
                    float inter = __fmul_rn(w, h);
                    if (inter > 0.0f) {
                        float denom = __fadd_rn(__fsub_rn(__fadd_rn(ai, ca[b]), inter), 1e-9f);
                        float iou = __fdiv_rn(inter, denom);
                        if (iou > NMS_T) {
                            u32 rj = cr[b];
                            u32 hi = ri > rj ? ri : rj;
                            u32 lo = ri > rj ? rj : ri;
                            pk = (hi << 16) | lo;
                            pred = true;
                        }
                    }
                }
                unsigned m = __ballot_sync(FULLM, pred);   // warp-aggregated emit
                if (pred) {
                    int leader = __ffs(m) - 1;
                    int bpos;
                    if (lane == leader) bpos = atomicAdd(&g_nedges, __popc(m));
                    bpos = __shfl_sync(m, bpos, leader);
                    int slot = bpos + __popc(m & ((1u << lane) - 1u));
                    if (slot < EDGE_CAP) g_edges[slot] = pk;
                }
            }
        }
    } else {
        // fallback (cold): row-wise over valid prefix via perm gathers
        for (int i = 1 + blockIdx.x; i < nv; i += NBLK) {
            float4 bi = g_box[g_perm[i]];
            if (!(bi.z > bi.x && bi.w > bi.y)) continue;
            float ai = __fmul_rn(__fsub_rn(bi.z, bi.x), __fsub_rn(bi.w, bi.y));
            for (int j = tid; j < i; j += NTHR) {
                float4 bj = g_box[g_perm[j]];
                float ltx = fmaxf(bi.x, bj.x);
                float lty = fmaxf(bi.y, bj.y);
                float rbx = fminf(bi.z, bj.z);
                float rby = fminf(bi.w, bj.w);
                float w = fmaxf(__fsub_rn(rbx, ltx), 0.0f);
                float h = fmaxf(__fsub_rn(rby, lty), 0.0f);
                float inter = __fmul_rn(w, h);
                if (inter > 0.0f) {
                    float aj = __fmul_rn(__fsub_rn(bj.z, bj.x), __fsub_rn(bj.w, bj.y));
                    float denom = __fadd_rn(__fsub_rn(__fadd_rn(ai, aj), inter), 1e-9f);
                    float iou = __fdiv_rn(inter, denom);
                    if (iou > NMS_T) {
                        int pos = atomicAdd(&g_nedges, 1);
                        if (pos < EDGE_CAP) g_edges[pos] = ((u32)i << 16) | (u32)j;
                    }
                }
            }
        }
    }

    // unmasked outputs for valid prefix + zero invalid rows + zero keep col
    {
        float4* ob = (float4*)out;
        float2* ok = (float2*)(out + 42000);
        const float2* ik = (const float2*)g_kps;
        const int gstride = NBLK * NTHR;
        for (int p = blockIdx.x * NTHR + tid; p < NTOT; p += gstride) {
            out[126000 + p] = 0.0f;               // keep column (fixup sets 1s)
            if (p < nv) {
                u32 n = g_perm[p];
                ob[p] = g_box[n];
                out[33600 + p] = __uint_as_float(g_key32[n]);
#pragma unroll
                for (int q = 0; q < 5; q++)
                    ok[p * 5 + q] = ik[n * 5 + q];
            } else {
                ob[p] = make_float4(0.f, 0.f, 0.f, 0.f);
                out[33600 + p] = 0.0f;
                float2 z2 = make_float2(0.f, 0.f);
#pragma unroll
                for (int q = 0; q < 5; q++)
                    ok[p * 5 + q] = z2;
            }
        }
    }

    // ---- last-block election (spin-free) ----
    __syncthreads();
    __threadfence();                            // release edges + output stores
    if (tid == 0) arrive_old = atomicAdd(&g_done2, 1u);
    __syncthreads();
    if (arrive_old != NBLK - 1) return;
    __threadfence();                            // acquire side

    // ======== last block: NMS fixpoint, ping-pong sup buffers ==============
    // keep[i] = valid[i] && !any((i,j) edge: keep[j]); unique fixpoint on the
    // j<i DAG; Jacobi iterate, "no change" = exact; NTOT+1 cap = hard bound.
    // Round r marks into sup[r%2]; the update pass clears the OTHER buffer
    // for the next round (2 edge passes/round instead of 3).
    {
        u32* es   = (u32*)sm;                   // [ESMEM]  64KB
        uc*  keep = (uc*)(es + ESMEM);          // [NTOT]
        uc*  supA = keep + NTOT;                // [NTOT]
        uc*  supB = supA + NTOT;                // [NTOT]

        int ne = g_nedges;
        if (ne > EDGE_CAP) ne = EDGE_CAP;
        bool use_s = (ne <= ESMEM);
        __syncthreads();                        // done with candidate table
        if (use_s)
            for (int e = tid; e < ne; e += NTHR) es[e] = g_edges[e];
        for (int p = tid; p < NTOT; p += NTHR) {
            keep[p] = (p < nv) ? 1 : 0;         // valid prefix
            supA[p] = 0;
            supB[p] = 0;
        }
        __syncthreads();
        const u32* E = use_s ? es : g_edges;

        for (int it = 0; it < NTOT + 1; it++) {
            uc* sc = (it & 1) ? supB : supA;    // mark target this round
            uc* sn = (it & 1) ? supA : supB;    // cleared for next round
            if (tid == 0) changed = 0;
            for (int e = tid; e < ne; e += NTHR) {           // mark
                u32 x = E[e];
                if (keep[x & 0xffffu]) sc[x >> 16] = 1;
            }
            __syncthreads();
            for (int e = tid; e < ne; e += NTHR) {           // update + clear
                int i = (int)(E[e] >> 16);
                uc nz = (!sc[i]) ? 1 : 0;       // i < nv by construction
                if (keep[i] != nz) { keep[i] = nz; changed = 1; }
                sn[i] = 0;
            }
            __syncthreads();
            int ch = changed;
            __syncthreads();
            if (!ch) break;
        }

        // fixup: kept rows -> keep=1; suppressed valid rows -> re-zero.
        float4* ob = (float4*)out;
        float2* ok = (float2*)(out + 42000);
        for (int p = tid; p < nv; p += NTHR) {
            if (keep[p]) {
                out[126000 + p] = 1.0f;
            } else {
                ob[p] = make_float4(0.f, 0.f, 0.f, 0.f);
                out[33600 + p] = 0.0f;
                float2 z2 = make_float2(0.f, 0.f);
#pragma unroll
                for (int q = 0; q < 5; q++)
                    ok[p * 5 + q] = z2;
            }
        }
        __syncthreads();
        if (tid == 0) g_done2 = 0;              // all arrivals observed; safe
    }
}

// ---------------------------------------------------------------------------
extern "C" void kernel_launch(void* const* d_in, const int* in_sizes, int n_in,
                              void* d_out, int out_size)
{
    const float *s0, *b0, *k0, *s1, *b1, *k1, *s2, *b2, *k2;
    // dict-insertion order (score0,bbox0,kps0,...) vs signature order
    if (n_in >= 9 && in_sizes[1] == 25600) {
        s0 = (const float*)d_in[0]; b0 = (const float*)d_in[1]; k0 = (const float*)d_in[2];
        s1 = (const float*)d_in[3]; b1 = (const float*)d_in[4]; k1 = (const float*)d_in[5];
        s2 = (const float*)d_in[6]; b2 = (const float*)d_in[7]; k2 = (const float*)d_in[8];
    } else {
        s0 = (const float*)d_in[0]; s1 = (const float*)d_in[1]; s2 = (const float*)d_in[2];
        b0 = (const float*)d_in[3]; b1 = (const float*)d_in[4]; b2 = (const float*)d_in[5];
        k0 = (const float*)d_in[6]; k1 = (const float*)d_in[7]; k2 = (const float*)d_in[8];
    }

    const int k1_smem = NTOT * 8 + NTOT * 4;             // 100,800 B (bitem+skey)
    const int k2_smem = ESMEM * 4 + 3 * NTOT;            // 90,736 B (nms > cand)
    cudaFuncSetAttribute(k1_decode_sort, cudaFuncAttributeMaxDynamicSharedMemorySize, k1_smem);
    cudaFuncSetAttribute(k2_edge_nms,    cudaFuncAttributeMaxDynamicSharedMemorySize, k2_smem);

    k1_decode_sort<<<NBLK, NTHR, k1_smem>>>(s0, b0, k0, s1, b1, k1, s2, b2, k2);
    k2_edge_nms<<<NBLK, NTHR, k2_smem>>>((float*)d_out);
}

// round 17
// speedup vs baseline: 3.8673x; 1.6620x over previous
#include <cuda_runtime.h>
#include <math.h>

// ---------------------------------------------------------------------------
// SCRFD post-processing, 3 graph nodes:
//   K1 (132x64):  decode (bit-exact) + keepflag init + inline candidate
//                 compaction (warp-ballot, order-free). Fully parallel.
//   K2 (132x1024): block 131 = counting-sort argsort -> g_perm (serial);
//                 blocks 0..130 = candidate pair sweep -> edge list (direction
//                 from pack compare, no ranks needed); last edge block = NMS
//                 fixpoint in candidate space -> clears g_keepflag[orig].
//                 Sort and edges+NMS run CONCURRENTLY.
//   K3 (33x256):  output: row p <- decoded[perm[p]] * keepflag, keep column,
//                 counter resets for next replay.
//
// Output layout (float32, 134400 elems):
//   [0:33600) boxes[8400,4] | [33600:42000) scores | [42000:126000) kps[8400,10]
//   | [126000:134400) keep
// ---------------------------------------------------------------------------

#define NTOT    8400
#define NBLK    132
#define NEDGEB  131          // edge blocks in K2 (block 131 sorts)
#define NTHR    1024
#define NBUCK   2048
#define SCORE_T 0.5f
#define NMS_T   0.4f
#define EDGE_CAP (1 << 22)
#define ESMEM   16384        // smem edge cache (ne bracketed <=16384 in R9/R13)
#define CANDSM  2048         // smem candidate table cap (expect ~1050)
#define FULLM   0xffffffffu

typedef unsigned long long u64;
typedef unsigned int u32;
typedef unsigned char uc;

__device__ float4 g_box[NTOT];        // decoded boxes (orig order)
__device__ float  g_kps[NTOT * 10];   // decoded keypoints (orig order)
__device__ u32    g_key32[NTOT];      // sigmoid f32 bits (positive)
__device__ uc     g_keepflag[NTOT];   // orig-index keep (init=valid; NMS clears)
__device__ u32    g_perm[NTOT];       // sorted pos -> orig index
__device__ float4 g_cbox[NTOT];       // candidate boxes (unordered compaction)
__device__ float  g_carea[NTOT];      // candidate areas
__device__ u64    g_cpack[NTOT];      // candidate order packs (key<<14)|(8399-n)
__device__ u32    g_corig[NTOT];      // candidate -> orig index
__device__ int    g_ncand;            // #candidates (valid & proper box)
__device__ int    g_nedges;
__device__ u32    g_edges[EDGE_CAP];  // (succ_c<<16)|pred_c candidate indices
__device__ u32    g_done2;            // K2 edge-block arrival counter (self-reset)

// ---------------------------------------------------------------------------
// K1: pure parallel decode + candidate compaction. 64 items per block.
__global__ void k1_decode(const float* __restrict__ s0, const float* __restrict__ b0, const float* __restrict__ k0,
                          const float* __restrict__ s1, const float* __restrict__ b1, const float* __restrict__ k1,
                          const float* __restrict__ s2, const float* __restrict__ b2, const float* __restrict__ k2)
{
    const int tid = threadIdx.x;
    const int lane = tid & 31;
    const int n = blockIdx.x * 64 + tid;
    bool in = (n < NTOT);

    bool pred = false;
    float4 bb;
    float area = 0.0f;
    u64 pack = 0;

    if (in) {
        const float *sp, *bp, *kp;
        int local, fw;
        float st;
        if (n < 6400)      { sp = s0; bp = b0; kp = k0; local = n;        fw = 80; st = 8.0f;  }
        else if (n < 8000) { sp = s1; bp = b1; kp = k1; local = n - 6400; fw = 40; st = 16.0f; }
        else               { sp = s2; bp = b2; kp = k2; local = n - 8000; fw = 20; st = 32.0f; }

        float px = (float)(local % fw) * st;   // exact (int * pow2)
        float py = (float)(local / fw) * st;

        // sigmoid in double: correctly-rounded-to-f32 -> monotone ordering
        // (matches JAX ordering; rel_err 4.3e-8 across R7-R16).
        float s = (float)(1.0 / (1.0 + exp(-(double)sp[local])));

        float4 d = ((const float4*)bp)[local]; // pow2 strides -> bit-exact
        bb.x = px - d.x * st;
        bb.y = py - d.y * st;
        bb.z = px + d.z * st;
        bb.w = py + d.w * st;
        g_box[n] = bb;

        const float2* kp2 = (const float2*)kp;
        float2* ko = (float2*)g_kps;
#pragma unroll
        for (int q = 0; q < 5; q++) {
            float2 kv = kp2[local * 5 + q];
            float2 kd;
            kd.x = px + kv.x * st;
            kd.y = py + kv.y * st;
            ko[n * 5 + q] = kd;
        }

        u32 key = __float_as_uint(s);          // positive -> uint order = float order
        g_key32[n] = key;
        bool valid = (s > SCORE_T);
        g_keepflag[n] = valid ? 1 : 0;         // NMS clears suppressed ones

        // candidate = valid AND proper (x2>x1 && y2>y1); improper boxes have
        // iou==0 with everything -> participate in no suppression edges.
        if (valid && bb.z > bb.x && bb.w > bb.y) {
            pred = true;
            area = __fmul_rn(__fsub_rn(bb.z, bb.x), __fsub_rn(bb.w, bb.y));
            pack = ((u64)key << 14) | (u32)(NTOT - 1 - n);   // strict total order
        }
    }

    unsigned m = __ballot_sync(FULLM, pred);   // warp-aggregated compaction
    if (pred) {
        int leader = __ffs(m) - 1;
        u32 bpos;
        if (lane == leader) bpos = atomicAdd((u32*)&g_ncand, (u32)__popc(m));
        bpos = __shfl_sync(m, bpos, leader);
        u32 slot = bpos + (u32)__popc(m & ((1u << lane) - 1u));
        g_cbox[slot]  = bb;
        g_carea[slot] = area;
        g_cpack[slot] = pack;
        g_corig[slot] = (u32)n;
    }
}

// ---------------------------------------------------------------------------
// K2: heterogeneous blocks. Block NBLK-1 sorts (independent); blocks 0..130
// compute edges over candidates; the last edge block runs NMS.
__global__ __launch_bounds__(NTHR, 1)
void k2_sort_edge_nms()
{
    extern __shared__ char dsm[];
    const int tid = threadIdx.x;
    const int lane = tid & 31;
    const int wid = tid >> 5;

    if (blockIdx.x == NBLK - 1) {
        // ================= SORTER BLOCK: exact stable argsort ==============
        // bucket(s) = floor(s*2048): mul by pow2 exact -> monotone; exact
        // within-bucket rank via pack (key<<14)|(8399-n). Output: g_perm.
        u64* sbitem = (u64*)dsm;                   // [NTOT]
        u32* skey   = (u32*)(dsm + NTOT * 8);      // [NTOT]
        __shared__ u32 hist[NBUCK], base[NBUCK], cur[NBUCK];
        __shared__ u32 wsum[32];

        for (int b = tid; b < NBUCK; b += NTHR) { hist[b] = 0; cur[b] = 0; }
        __syncthreads();

        for (int n = tid; n < NTOT; n += NTHR) {
            u32 key = g_key32[n];
            skey[n] = key;
            float s = __uint_as_float(key);
            u32 b = (u32)(s * (float)NBUCK);
            if (b > NBUCK - 1) b = NBUCK - 1;
            atomicAdd(&hist[b], 1u);
        }
        __syncthreads();

        // descending exclusive scan via warp shuffles (t owns desc {2t,2t+1})
        {
            u32 l0 = hist[NBUCK - 1 - (tid * 2)];
            u32 l1 = hist[NBUCK - 1 - (tid * 2 + 1)];
            u32 s2 = l0 + l1;
            u32 v = s2;
#pragma unroll
            for (int off = 1; off < 32; off <<= 1) {
                u32 t = __shfl_up_sync(FULLM, v, off);
                if (lane >= off) v += t;
            }
            if (lane == 31) wsum[wid] = v;
            __syncthreads();
            if (wid == 0) {
                u32 w = wsum[lane];
                u32 vv = w;
#pragma unroll
                for (int off = 1; off < 32; off <<= 1) {
                    u32 t = __shfl_up_sync(FULLM, vv, off);
                    if (lane >= off) vv += t;
                }
                wsum[lane] = vv - w;            // exclusive warp base
            }
            __syncthreads();
            u32 excl = wsum[wid] + (v - s2);
            base[NBUCK - 1 - (tid * 2)]     = excl;
            base[NBUCK - 1 - (tid * 2 + 1)] = excl + l0;
        }
        __syncthreads();

        for (int n = tid; n < NTOT; n += NTHR) {
            u32 key = skey[n];
            float s = __uint_as_float(key);
            u32 b = (u32)(s * (float)NBUCK);
            if (b > NBUCK - 1) b = NBUCK - 1;
            u32 slot = atomicAdd(&cur[b], 1u);
            sbitem[base[b] + slot] = ((u64)key << 14) | (u32)(NTOT - 1 - n);
        }
        __syncthreads();

        for (int n = tid; n < NTOT; n += NTHR) {
            u32 key = skey[n];
            float s = __uint_as_float(key);
            u32 b = (u32)(s * (float)NBUCK);
            if (b > NBUCK - 1) b = NBUCK - 1;
            u32 bs = base[b], L = hist[b];
            u64 me = ((u64)key << 14) | (u32)(NTOT - 1 - n);
            u32 c = 0;
            for (u32 l = 0; l < L; l++)
                c += (sbitem[bs + l] > me) ? 1u : 0u;
            g_perm[bs + c] = (u32)n;
        }
        return;
    }

    // ===================== EDGE BLOCKS (0..130) ============================
    float4* cb  = (float4*)dsm;                     // [CANDSM] 32KB
    float*  ca  = (float*)(dsm + CANDSM * 16);      // [CANDSM]  8KB
    u64*    cpk = (u64*)(dsm + CANDSM * 20);        // [CANDSM] 16KB
    __shared__ u32 arrive_old;
    __shared__ int changed;

    const int nc = g_ncand;
    const bool small = (nc <= CANDSM);

    if (small) {
        for (int t = tid; t < nc; t += NTHR) {
            cb[t]  = g_cbox[t];
            ca[t]  = g_carea[t];
            cpk[t] = g_cpack[t];
        }
        __syncthreads();
    }

    // pair sweep; IoU replicates JAX bit-for-bit (rn intrinsics, no FMA).
    // Edge direction from pack compare: pred = larger pack (earlier in sort).
    for (int a = blockIdx.x; a < nc; a += NEDGEB) {
        float4 bi = small ? cb[a] : g_cbox[a];
        float  ai = small ? ca[a] : g_carea[a];
        u64    pi = small ? cpk[a] : g_cpack[a];
        for (int b0 = 0; b0 < a; b0 += NTHR) {
            int b = b0 + tid;
            bool in = (b < a);
            bool hit = false;
            u32 pk = 0;
            if (in) {
                float4 bj = small ? cb[b] : g_cbox[b];
                float ltx = fmaxf(bi.x, bj.x);
                float lty = fmaxf(bi.y, bj.y);
                float rbx = fminf(bi.z, bj.z);
                float rby = fminf(bi.w, bj.w);
                float w = fmaxf(__fsub_rn(rbx, ltx), 0.0f);
                float h = fmaxf(__fsub_rn(rby, lty), 0.0f);
                float inter = __fmul_rn(w, h);
                if (inter > 0.0f) {
                    float aj = small ? ca[b] : g_carea[b];
                    float denom = __fadd_rn(__fsub_rn(__fadd_rn(ai, aj), inter), 1e-9f);
                    float iou = __fdiv_rn(inter, denom);
                    if (iou > NMS_T) {
                        u64 pj = small ? cpk[b] : g_cpack[b];
                        u32 succ = (pi < pj) ? (u32)a : (u32)b;  // smaller pack = later
                        u32 prd  = (pi < pj) ? (u32)b : (u32)a;
                        pk = (succ << 16) | prd;
                        hit = true;
                    }
                }
            }
            unsigned m = __ballot_sync(FULLM, hit);    // warp-aggregated emit
            if (hit) {
                int leader = __ffs(m) - 1;
                int bpos;
                if (lane == leader) bpos = atomicAdd(&g_nedges, __popc(m));
                bpos = __shfl_sync(m, bpos, leader);
                int slot = bpos + __popc(m & ((1u << lane) - 1u));
                if (slot < EDGE_CAP) g_edges[slot] = pk;
            }
        }
    }

    // ---- last-edge-block election (spin-free) ----
    __syncthreads();
    __threadfence();                            // release edge stores
    if (tid == 0) arrive_old = atomicAdd(&g_done2, 1u);
    __syncthreads();
    if (arrive_old != NEDGEB - 1) return;
    __threadfence();                            // acquire side

    // ===================== NMS (candidate space) ===========================
    // keep[c] = !any(edge (c,j): keep[j]); unique fixpoint on the pack-order
    // DAG; ping-pong Jacobi, "no change" = exact; NTOT+1 cap = hard bound.
    {
        u32* es   = (u32*)dsm;                  // [ESMEM]  64KB (overlay)
        uc*  keep = (uc*)(es + ESMEM);          // [NTOT]
        uc*  supA = keep + NTOT;                // [NTOT]
        uc*  supB = supA + NTOT;                // [NTOT]

        int ne = g_nedges;
        if (ne > EDGE_CAP) ne = EDGE_CAP;
        bool use_s = (ne <= ESMEM);
        __syncthreads();                        // done with candidate table
        if (use_s)
            for (int e = tid; e < ne; e += NTHR) es[e] = g_edges[e];
        for (int c = tid; c < nc; c += NTHR) {
            keep[c] = 1;                        // all candidates are valid
            supA[c] = 0;
            supB[c] = 0;
        }
        __syncthreads();
        const u32* E = use_s ? es : g_edges;

        for (int it = 0; it < NTOT + 1; it++) {
            uc* sc = (it & 1) ? supB : supA;
            uc* sn = (it & 1) ? supA : supB;
            if (tid == 0) changed = 0;
            for (int e = tid; e < ne; e += NTHR) {           // mark
                u32 x = E[e];
                if (keep[x & 0xffffu]) sc[x >> 16] = 1;
            }
            __syncthreads();
            for (int e = tid; e < ne; e += NTHR) {           // update + clear
                int i = (int)(E[e] >> 16);
                uc nz = (!sc[i]) ? 1 : 0;
                if (keep[i] != nz) { keep[i] = nz; changed = 1; }
                sn[i] = 0;
            }
            __syncthreads();
            int ch = changed;
            __syncthreads();
            if (!ch) break;
        }

        // clear keepflag for suppressed candidates (orig-index space)
        for (int c = tid; c < nc; c += NTHR)
            if (!keep[c]) g_keepflag[g_corig[c]] = 0;
        __syncthreads();
        if (tid == 0) g_done2 = 0;              // all arrivals observed; safe
    }
}

// ---------------------------------------------------------------------------
// K3: output writer. Row p <- decoded[perm[p]] * keepflag; counter resets.
// Multiply matches reference (boxes*m etc.) exactly for m in {0.0f, 1.0f}.
__global__ void k3_output(float* __restrict__ out)
{
    int p = blockIdx.x * blockDim.x + threadIdx.x;
    if (p == 0) { g_ncand = 0; g_nedges = 0; }   // reset for next replay
    if (p >= NTOT) return;

    u32 n = g_perm[p];
    float m = g_keepflag[n] ? 1.0f : 0.0f;

    float4 b = g_box[n];
    float4 bo;
    bo.x = b.x * m; bo.y = b.y * m; bo.z = b.z * m; bo.w = b.w * m;
    ((float4*)out)[p] = bo;

    out[33600 + p] = __uint_as_float(g_key32[n]) * m;

    const float2* ik = (const float2*)g_kps;
    float2* ok = (float2*)(out + 42000);
#pragma unroll
    for (int q = 0; q < 5; q++) {
        float2 kv = ik[n * 5 + q];
        kv.x *= m; kv.y *= m;
        ok[p * 5 + q] = kv;
    }
    out[126000 + p] = m;
}

// ---------------------------------------------------------------------------
extern "C" void kernel_launch(void* const* d_in, const int* in_sizes, int n_in,
                              void* d_out, int out_size)
{
    const float *s0, *b0, *k0, *s1, *b1, *k1, *s2, *b2, *k2;
    // dict-insertion order (score0,bbox0,kps0,...) vs signature order
    if (n_in >= 9 && in_sizes[1] == 25600) {
        s0 = (const float*)d_in[0]; b0 = (const float*)d_in[1]; k0 = (const float*)d_in[2];
        s1 = (const float*)d_in[3]; b1 = (const float*)d_in[4]; k1 = (const float*)d_in[5];
        s2 = (const float*)d_in[6]; b2 = (const float*)d_in[7]; k2 = (const float*)d_in[8];
    } else {
        s0 = (const float*)d_in[0]; s1 = (const float*)d_in[1]; s2 = (const float*)d_in[2];
        b0 = (const float*)d_in[3]; b1 = (const float*)d_in[4]; b2 = (const float*)d_in[5];
        k0 = (const float*)d_in[6]; k1 = (const float*)d_in[7]; k2 = (const float*)d_in[8];
    }

    // K2 dynamic smem must cover: sorter (bitem 67.2K + skey 33.6K = 100.8K),
    // edge table (56K), NMS overlay (64K + 3*8.4K = 89.2K) -> 100,800 B.
    const int k2_smem = NTOT * 8 + NTOT * 4;
    cudaFuncSetAttribute(k2_sort_edge_nms, cudaFuncAttributeMaxDynamicSharedMemorySize, k2_smem);

    k1_decode<<<NBLK, 64>>>(s0, b0, k0, s1, b1, k1, s2, b2, k2);
    k2_sort_edge_nms<<<NBLK, NTHR, k2_smem>>>();
    k3_output<<<(NTOT + 255) / 256, 256>>>((float*)d_out);
}